// round 1
// baseline (speedup 1.0000x reference)
#include <cuda_runtime.h>
#include <math_constants.h>
#include <cstdint>

#define SEQ   2048
#define HDIM  4096
#define NH    32
#define NKV   8
#define HD    128
#define KINT  1024          // HDIM / 4 bytes packed per int
#define SCALE 0.08838834764831845f   // 1/sqrt(128)

// ---------------------------------------------------------------------------
// Scratch (static device globals; no runtime allocation)
// ---------------------------------------------------------------------------
__device__ int   g_xq[SEQ * KINT];          // quantized hidden (int8 packed)
__device__ float g_sx[SEQ];
__device__ int   g_wq[(NH * HD) * KINT];
__device__ float g_swq[NH * HD];
__device__ int   g_wk[(NKV * HD) * KINT];
__device__ float g_swk[NKV * HD];
__device__ int   g_wv[(NKV * HD) * KINT];
__device__ float g_swv[NKV * HD];
__device__ int   g_wo[HDIM * KINT];
__device__ float g_swo[HDIM];
__device__ float g_q[SEQ * NH * HD];
__device__ float g_k[SEQ * NKV * HD];
__device__ float g_v[SEQ * NKV * HD];
__device__ float g_attn[SEQ * NH * HD];
__device__ int   g_aq[SEQ * KINT];
__device__ float g_sa[SEQ];

// ---------------------------------------------------------------------------
// Per-row fake-quant: amax/127 scale, round-half-even, pack 4x int8 into int
// One block per row of 4096 floats. 256 threads, 16 floats each.
// ---------------------------------------------------------------------------
__global__ void quant_rows_kernel(const float* __restrict__ in,
                                  int* __restrict__ outp,
                                  float* __restrict__ scales) {
    const int row = blockIdx.x;
    const int t = threadIdx.x;
    const float4* inr = (const float4*)(in + (size_t)row * HDIM);

    float4 v[4];
    float amax = 0.f;
#pragma unroll
    for (int l = 0; l < 4; l++) {
        v[l] = inr[t + 256 * l];
        amax = fmaxf(amax, fmaxf(fmaxf(fabsf(v[l].x), fabsf(v[l].y)),
                                 fmaxf(fabsf(v[l].z), fabsf(v[l].w))));
    }
    __shared__ float red[256];
    red[t] = amax;
    __syncthreads();
#pragma unroll
    for (int st = 128; st > 0; st >>= 1) {
        if (t < st) red[t] = fmaxf(red[t], red[t + st]);
        __syncthreads();
    }
    float s = red[0] / 127.0f;
    s = fmaxf(s, 1e-8f);
    if (t == 0) scales[row] = s;

#pragma unroll
    for (int l = 0; l < 4; l++) {
        float4 x = v[l];
        int a = (int)fminf(fmaxf(rintf(x.x / s), -128.f), 127.f);
        int b = (int)fminf(fmaxf(rintf(x.y / s), -128.f), 127.f);
        int c = (int)fminf(fmaxf(rintf(x.z / s), -128.f), 127.f);
        int d = (int)fminf(fmaxf(rintf(x.w / s), -128.f), 127.f);
        int p = (a & 0xFF) | ((b & 0xFF) << 8) | ((c & 0xFF) << 16) | (d << 24);
        outp[(size_t)row * KINT + t + 256 * l] = p;
    }
}

// ---------------------------------------------------------------------------
// Int8 GEMM via dp4a: Y[m][n] = sa[m]*sb[n] * dot_i8(A[m,:], B[n,:]), K=4096
// A: [M][KINT] packed, B: [N][KINT] packed. Tiles 64x64, BK=16 ints.
// 256 threads, 4x4 outputs per thread.
// ---------------------------------------------------------------------------
__global__ void gemm_q8_kernel(const int* __restrict__ A, const float* __restrict__ sa,
                               const int* __restrict__ B, const float* __restrict__ sb,
                               float* __restrict__ Y, int N) {
    __shared__ int As[16][68];
    __shared__ int Bs[16][68];

    const int tid = threadIdx.x;
    const int tn = tid & 15;     // 0..15
    const int tm = tid >> 4;     // 0..15
    const int m0 = blockIdx.y * 64;
    const int n0 = blockIdx.x * 64;

    int acc[4][4] = {};

    const int* Ag = A + (size_t)(m0 + tm) * KINT + tn;
    const int* Bg = B + (size_t)(n0 + tm) * KINT + tn;

    for (int k0 = 0; k0 < KINT; k0 += 16) {
#pragma unroll
        for (int l = 0; l < 4; l++) {
            As[tn][tm + 16 * l] = Ag[(size_t)(16 * l) * KINT + k0];
            Bs[tn][tm + 16 * l] = Bg[(size_t)(16 * l) * KINT + k0];
        }
        __syncthreads();
#pragma unroll
        for (int k = 0; k < 16; k++) {
            int4 a = *(const int4*)&As[k][tm * 4];
            int4 b = *(const int4*)&Bs[k][tn * 4];
            acc[0][0] = __dp4a(a.x, b.x, acc[0][0]);
            acc[0][1] = __dp4a(a.x, b.y, acc[0][1]);
            acc[0][2] = __dp4a(a.x, b.z, acc[0][2]);
            acc[0][3] = __dp4a(a.x, b.w, acc[0][3]);
            acc[1][0] = __dp4a(a.y, b.x, acc[1][0]);
            acc[1][1] = __dp4a(a.y, b.y, acc[1][1]);
            acc[1][2] = __dp4a(a.y, b.z, acc[1][2]);
            acc[1][3] = __dp4a(a.y, b.w, acc[1][3]);
            acc[2][0] = __dp4a(a.z, b.x, acc[2][0]);
            acc[2][1] = __dp4a(a.z, b.y, acc[2][1]);
            acc[2][2] = __dp4a(a.z, b.z, acc[2][2]);
            acc[2][3] = __dp4a(a.z, b.w, acc[2][3]);
            acc[3][0] = __dp4a(a.w, b.x, acc[3][0]);
            acc[3][1] = __dp4a(a.w, b.y, acc[3][1]);
            acc[3][2] = __dp4a(a.w, b.z, acc[3][2]);
            acc[3][3] = __dp4a(a.w, b.w, acc[3][3]);
        }
        __syncthreads();
    }

    float sm[4], sn[4];
#pragma unroll
    for (int i = 0; i < 4; i++) sm[i] = sa[m0 + tm * 4 + i];
#pragma unroll
    for (int j = 0; j < 4; j++) sn[j] = sb[n0 + tn * 4 + j];
#pragma unroll
    for (int i = 0; i < 4; i++) {
        float4 o;
        o.x = (float)acc[i][0] * sm[i] * sn[0];
        o.y = (float)acc[i][1] * sm[i] * sn[1];
        o.z = (float)acc[i][2] * sm[i] * sn[2];
        o.w = (float)acc[i][3] * sm[i] * sn[3];
        *(float4*)&Y[(size_t)(m0 + tm * 4 + i) * N + n0 + tn * 4] = o;
    }
}

// ---------------------------------------------------------------------------
// RoPE in-place on [S][nh*128]: pairs (d, d+64) per head
// ---------------------------------------------------------------------------
__global__ void rope_kernel(float* __restrict__ x, const float* __restrict__ cosb,
                            const float* __restrict__ sinb, int nh) {
    int idx = blockIdx.x * blockDim.x + threadIdx.x;
    int total = SEQ * nh * 64;
    if (idx >= total) return;
    int d = idx & 63;
    int h = (idx >> 6) % nh;
    int t = idx / (nh * 64);
    float c = cosb[t * 128 + d];
    float s = sinb[t * 128 + d];
    float* p = x + (size_t)t * nh * 128 + h * 128 + d;
    float x1 = p[0], x2 = p[64];
    p[0]  = x1 * c - x2 * s;
    p[64] = x2 * c + x1 * s;
}

// ---------------------------------------------------------------------------
// Causal GQA flash attention, fp32 online softmax.
// Grid: (qblock=32, head=32). Block: 512 threads (16 warps).
// Each warp owns 4 q rows; 64x64 KV tile staged in 64KB dynamic smem.
// ---------------------------------------------------------------------------
#define UPD(mi, li, a, s)                                      \
    {                                                          \
        float mn = fmaxf(mi, s);                               \
        float f = __expf(mi - mn);                             \
        float p = __expf(s - mn);                              \
        li = li * f + p;                                       \
        a.x = a.x * f + p * v4.x;                              \
        a.y = a.y * f + p * v4.y;                              \
        a.z = a.z * f + p * v4.z;                              \
        a.w = a.w * f + p * v4.w;                              \
        mi = mn;                                               \
    }

__global__ void attn_kernel() {
    extern __shared__ float sh[];
    float* Ks = sh;
    float* Vs = sh + 64 * 128;

    const int qb = blockIdx.x;
    const int h = blockIdx.y;
    const int kvh = h >> 2;
    const int tid = threadIdx.x;
    const int w = tid >> 5;
    const int lane = tid & 31;
    const int m0 = qb * 64 + w * 4;
    const int col = h * 128 + lane * 4;

    float4 qr0 = *(const float4*)&g_q[(size_t)(m0 + 0) * (NH * HD) + col];
    float4 qr1 = *(const float4*)&g_q[(size_t)(m0 + 1) * (NH * HD) + col];
    float4 qr2 = *(const float4*)&g_q[(size_t)(m0 + 2) * (NH * HD) + col];
    float4 qr3 = *(const float4*)&g_q[(size_t)(m0 + 3) * (NH * HD) + col];

    float mi0 = -CUDART_INF_F, mi1 = -CUDART_INF_F, mi2 = -CUDART_INF_F, mi3 = -CUDART_INF_F;
    float li0 = 0.f, li1 = 0.f, li2 = 0.f, li3 = 0.f;
    float4 a0 = {0, 0, 0, 0}, a1 = {0, 0, 0, 0}, a2 = {0, 0, 0, 0}, a3 = {0, 0, 0, 0};

    for (int kt = 0; kt <= qb; kt++) {
        __syncthreads();
#pragma unroll
        for (int l = 0; l < 4; l++) {
            int f = tid + 512 * l;          // float4 index within 64x32
            int j = f >> 5;
            int c = (f & 31) << 2;
            size_t g = (size_t)(kt * 64 + j) * (NKV * HD) + (size_t)kvh * HD + c;
            *(float4*)&Ks[j * 128 + c] = *(const float4*)&g_k[g];
            *(float4*)&Vs[j * 128 + c] = *(const float4*)&g_v[g];
        }
        __syncthreads();

        const bool diag = (kt == qb);
#pragma unroll 1
        for (int j = 0; j < 64; j++) {
            int key = kt * 64 + j;
            if (diag && key > m0 + 3) break;

            float4 k4 = *(const float4*)&Ks[j * 128 + lane * 4];
            float p0 = qr0.x * k4.x + qr0.y * k4.y + qr0.z * k4.z + qr0.w * k4.w;
            float p1 = qr1.x * k4.x + qr1.y * k4.y + qr1.z * k4.z + qr1.w * k4.w;
            float p2 = qr2.x * k4.x + qr2.y * k4.y + qr2.z * k4.z + qr2.w * k4.w;
            float p3 = qr3.x * k4.x + qr3.y * k4.y + qr3.z * k4.z + qr3.w * k4.w;
#pragma unroll
            for (int off = 16; off; off >>= 1) {
                p0 += __shfl_xor_sync(0xffffffffu, p0, off);
                p1 += __shfl_xor_sync(0xffffffffu, p1, off);
                p2 += __shfl_xor_sync(0xffffffffu, p2, off);
                p3 += __shfl_xor_sync(0xffffffffu, p3, off);
            }
            float4 v4 = *(const float4*)&Vs[j * 128 + lane * 4];
            p0 *= SCALE; p1 *= SCALE; p2 *= SCALE; p3 *= SCALE;

            if (!diag || key <= m0 + 0) UPD(mi0, li0, a0, p0);
            if (!diag || key <= m0 + 1) UPD(mi1, li1, a1, p1);
            if (!diag || key <= m0 + 2) UPD(mi2, li2, a2, p2);
            if (!diag || key <= m0 + 3) UPD(mi3, li3, a3, p3);
        }
    }

    float4 o;
    o.x = a0.x / li0; o.y = a0.y / li0; o.z = a0.z / li0; o.w = a0.w / li0;
    *(float4*)&g_attn[(size_t)(m0 + 0) * (NH * HD) + col] = o;
    o.x = a1.x / li1; o.y = a1.y / li1; o.z = a1.z / li1; o.w = a1.w / li1;
    *(float4*)&g_attn[(size_t)(m0 + 1) * (NH * HD) + col] = o;
    o.x = a2.x / li2; o.y = a2.y / li2; o.z = a2.z / li2; o.w = a2.w / li2;
    *(float4*)&g_attn[(size_t)(m0 + 2) * (NH * HD) + col] = o;
    o.x = a3.x / li3; o.y = a3.y / li3; o.z = a3.z / li3; o.w = a3.w / li3;
    *(float4*)&g_attn[(size_t)(m0 + 3) * (NH * HD) + col] = o;
}

// ---------------------------------------------------------------------------
// Host launch
// ---------------------------------------------------------------------------
extern "C" void kernel_launch(void* const* d_in, const int* in_sizes, int n_in,
                              void* d_out, int out_size) {
    (void)in_sizes; (void)n_in; (void)out_size;
    const float* hx   = (const float*)d_in[0];
    const float* cosb = (const float*)d_in[1];
    const float* sinb = (const float*)d_in[2];
    const float* Wq   = (const float*)d_in[3];
    const float* Wk   = (const float*)d_in[4];
    const float* Wv   = (const float*)d_in[5];
    const float* Wo   = (const float*)d_in[6];
    float* out = (float*)d_out;

    void *p_xq, *p_sx, *p_wq, *p_swq, *p_wk, *p_swk, *p_wv, *p_swv, *p_wo, *p_swo;
    void *p_q, *p_k, *p_v, *p_attn, *p_aq, *p_sa;
    cudaGetSymbolAddress(&p_xq, g_xq);   cudaGetSymbolAddress(&p_sx, g_sx);
    cudaGetSymbolAddress(&p_wq, g_wq);   cudaGetSymbolAddress(&p_swq, g_swq);
    cudaGetSymbolAddress(&p_wk, g_wk);   cudaGetSymbolAddress(&p_swk, g_swk);
    cudaGetSymbolAddress(&p_wv, g_wv);   cudaGetSymbolAddress(&p_swv, g_swv);
    cudaGetSymbolAddress(&p_wo, g_wo);   cudaGetSymbolAddress(&p_swo, g_swo);
    cudaGetSymbolAddress(&p_q, g_q);     cudaGetSymbolAddress(&p_k, g_k);
    cudaGetSymbolAddress(&p_v, g_v);     cudaGetSymbolAddress(&p_attn, g_attn);
    cudaGetSymbolAddress(&p_aq, g_aq);   cudaGetSymbolAddress(&p_sa, g_sa);

    // 1. fake-quant activations and weights (per-row int8 + scale)
    quant_rows_kernel<<<SEQ, 256>>>(hx, (int*)p_xq, (float*)p_sx);
    quant_rows_kernel<<<NH * HD, 256>>>(Wq, (int*)p_wq, (float*)p_swq);
    quant_rows_kernel<<<NKV * HD, 256>>>(Wk, (int*)p_wk, (float*)p_swk);
    quant_rows_kernel<<<NKV * HD, 256>>>(Wv, (int*)p_wv, (float*)p_swv);
    quant_rows_kernel<<<HDIM, 256>>>(Wo, (int*)p_wo, (float*)p_swo);

    // 2. QKV projections (exact int8 GEMM, scaled epilogue)
    gemm_q8_kernel<<<dim3((NH * HD) / 64, SEQ / 64), 256>>>(
        (const int*)p_xq, (const float*)p_sx, (const int*)p_wq, (const float*)p_swq,
        (float*)p_q, NH * HD);
    gemm_q8_kernel<<<dim3((NKV * HD) / 64, SEQ / 64), 256>>>(
        (const int*)p_xq, (const float*)p_sx, (const int*)p_wk, (const float*)p_swk,
        (float*)p_k, NKV * HD);
    gemm_q8_kernel<<<dim3((NKV * HD) / 64, SEQ / 64), 256>>>(
        (const int*)p_xq, (const float*)p_sx, (const int*)p_wv, (const float*)p_swv,
        (float*)p_v, NKV * HD);

    // 3. RoPE
    rope_kernel<<<(SEQ * NH * 64 + 255) / 256, 256>>>((float*)p_q, cosb, sinb, NH);
    rope_kernel<<<(SEQ * NKV * 64 + 255) / 256, 256>>>((float*)p_k, cosb, sinb, NKV);

    // 4. causal GQA flash attention
    cudaFuncSetAttribute(attn_kernel, cudaFuncAttributeMaxDynamicSharedMemorySize, 65536);
    attn_kernel<<<dim3(SEQ / 64, NH), 512, 65536>>>();

    // 5. fake-quant attention output, then O projection into d_out
    quant_rows_kernel<<<SEQ, 256>>>((const float*)p_attn, (int*)p_aq, (float*)p_sa);
    gemm_q8_kernel<<<dim3(HDIM / 64, SEQ / 64), 256>>>(
        (const int*)p_aq, (const float*)p_sa, (const int*)p_wo, (const float*)p_swo,
        out, HDIM);
}

// round 2
// speedup vs baseline: 1.2340x; 1.2340x over previous
#include <cuda_runtime.h>
#include <math_constants.h>
#include <cstdint>

#define SEQ   2048
#define HDIM  4096
#define NH    32
#define NKV   8
#define HD    128
#define KINT  1024          // HDIM / 4 bytes packed per int
#define SCALE 0.08838834764831845f   // 1/sqrt(128)

// ---------------------------------------------------------------------------
// Scratch (static device globals; no runtime allocation)
// ---------------------------------------------------------------------------
__device__ int   g_xq[SEQ * KINT];          // quantized hidden (int8 packed)
__device__ float g_sx[SEQ];
__device__ int   g_wq[(NH * HD) * KINT];
__device__ float g_swq[NH * HD];
__device__ int   g_wk[(NKV * HD) * KINT];
__device__ float g_swk[NKV * HD];
__device__ int   g_wv[(NKV * HD) * KINT];
__device__ float g_swv[NKV * HD];
__device__ int   g_wo[HDIM * KINT];
__device__ float g_swo[HDIM];
__device__ float g_q[SEQ * NH * HD];
__device__ float g_k[SEQ * NKV * HD];
__device__ float g_v[SEQ * NKV * HD];
__device__ float g_attn[SEQ * NH * HD];
__device__ int   g_aq[SEQ * KINT];
__device__ float g_sa[SEQ];

// ---------------------------------------------------------------------------
// Per-row fake-quant: amax/127 scale, round-half-even, pack 4x int8 into int.
// IEEE-exact division (__fdiv_rn) so int rounding matches the fp32 reference
// even when the rest of the TU is compiled with fast-math.
// ---------------------------------------------------------------------------
__global__ void quant_rows_kernel(const float* __restrict__ in,
                                  int* __restrict__ outp,
                                  float* __restrict__ scales) {
    const int row = blockIdx.x;
    const int t = threadIdx.x;
    const float4* inr = (const float4*)(in + (size_t)row * HDIM);

    float4 v[4];
    float amax = 0.f;
#pragma unroll
    for (int l = 0; l < 4; l++) {
        v[l] = inr[t + 256 * l];
        amax = fmaxf(amax, fmaxf(fmaxf(fabsf(v[l].x), fabsf(v[l].y)),
                                 fmaxf(fabsf(v[l].z), fabsf(v[l].w))));
    }
    __shared__ float red[256];
    red[t] = amax;
    __syncthreads();
#pragma unroll
    for (int st = 128; st > 0; st >>= 1) {
        if (t < st) red[t] = fmaxf(red[t], red[t + st]);
        __syncthreads();
    }
    float s = __fdiv_rn(red[0], 127.0f);
    s = fmaxf(s, 1e-8f);
    if (t == 0) scales[row] = s;

#pragma unroll
    for (int l = 0; l < 4; l++) {
        float4 x = v[l];
        int a = (int)fminf(fmaxf(rintf(__fdiv_rn(x.x, s)), -128.f), 127.f);
        int b = (int)fminf(fmaxf(rintf(__fdiv_rn(x.y, s)), -128.f), 127.f);
        int c = (int)fminf(fmaxf(rintf(__fdiv_rn(x.z, s)), -128.f), 127.f);
        int d = (int)fminf(fmaxf(rintf(__fdiv_rn(x.w, s)), -128.f), 127.f);
        int p = (a & 0xFF) | ((b & 0xFF) << 8) | ((c & 0xFF) << 16) | (d << 24);
        outp[(size_t)row * KINT + t + 256 * l] = p;
    }
}

// ---------------------------------------------------------------------------
// Int8 tensor-core GEMM: Y[m][n] = sa[m]*sb[n] * dot_i8(A[m,:], B[n,:])
// mma.sync.m16n8k32 s8, 128x128 tiles, BK=64 bytes, cp.async double buffer.
// 256 threads = 8 warps in a 2x4 grid; each warp owns a 64x32 output tile.
// Smem rows padded to 20 ints (80B): LDS bank = (20*r + c) mod 32 is a
// permutation over the warp -> conflict-free fragment loads.
// ---------------------------------------------------------------------------
#define SMS 20   // smem row stride in ints

__device__ __forceinline__ void cp_async16(void* smem, const void* g) {
    uint32_t s = (uint32_t)__cvta_generic_to_shared(smem);
    asm volatile("cp.async.cg.shared.global [%0], [%1], 16;\n" :: "r"(s), "l"(g));
}

__device__ __forceinline__ void mma_i8(int& c0, int& c1, int& c2, int& c3,
                                       int a0, int a1, int a2, int a3,
                                       int b0, int b1) {
    asm volatile(
        "mma.sync.aligned.m16n8k32.row.col.s32.s8.s8.s32 "
        "{%0,%1,%2,%3}, {%4,%5,%6,%7}, {%8,%9}, {%0,%1,%2,%3};\n"
        : "+r"(c0), "+r"(c1), "+r"(c2), "+r"(c3)
        : "r"(a0), "r"(a1), "r"(a2), "r"(a3), "r"(b0), "r"(b1));
}

__global__ __launch_bounds__(256, 2)
void gemm_i8mma_kernel(const int* __restrict__ A, const float* __restrict__ sa,
                       const int* __restrict__ B, const float* __restrict__ sb,
                       float* __restrict__ Y, int N) {
    __shared__ int As[2][128 * SMS];
    __shared__ int Bs[2][128 * SMS];

    const int tid = threadIdx.x;
    const int warp = tid >> 5;
    const int lane = tid & 31;
    const int wm = warp >> 2;        // 0..1
    const int wn = warp & 3;         // 0..3
    const int lr = lane >> 2;        // 0..7
    const int c  = lane & 3;         // 0..3
    const int m0 = blockIdx.y * 128;
    const int n0 = blockIdx.x * 128;

    // global->smem load mapping: 512 int4 per operand tile, 2 per thread
    const int r0g = tid >> 2;            // rows tid/4 and tid/4+64
    const int ch  = tid & 3;             // 16-byte chunk within 64B row

    const int* Ag0 = A + (size_t)(m0 + r0g) * KINT + ch * 4;
    const int* Ag1 = A + (size_t)(m0 + r0g + 64) * KINT + ch * 4;
    const int* Bg0 = B + (size_t)(n0 + r0g) * KINT + ch * 4;
    const int* Bg1 = B + (size_t)(n0 + r0g + 64) * KINT + ch * 4;
    int* As0 = &As[0][r0g * SMS + ch * 4];
    int* As1 = &As[0][(r0g + 64) * SMS + ch * 4];
    int* Bs0 = &Bs[0][r0g * SMS + ch * 4];
    int* Bs1 = &Bs[0][(r0g + 64) * SMS + ch * 4];
    const int bufstride = 128 * SMS;

    int acc[4][4][4] = {};

    // prologue: load tile 0
    cp_async16(As0, Ag0);
    cp_async16(As1, Ag1);
    cp_async16(Bs0, Bg0);
    cp_async16(Bs1, Bg1);
    asm volatile("cp.async.commit_group;\n");

    const int* Afrag = &As[0][(wm * 64 + lr) * SMS + c];
    const int* Bfrag = &Bs[0][(wn * 32 + lr) * SMS + c];

    for (int it = 0; it < 64; it++) {
        int cur = it & 1;
        if (it < 63) {
            int nb = (it + 1) & 1;
            int ko = (it + 1) * 16;
            cp_async16(As0 + nb * bufstride, Ag0 + ko);
            cp_async16(As1 + nb * bufstride, Ag1 + ko);
            cp_async16(Bs0 + nb * bufstride, Bg0 + ko);
            cp_async16(Bs1 + nb * bufstride, Bg1 + ko);
            asm volatile("cp.async.commit_group;\n");
            asm volatile("cp.async.wait_group 1;\n");
        } else {
            asm volatile("cp.async.wait_group 0;\n");
        }
        __syncthreads();

        const int* Af = Afrag + cur * bufstride;
        const int* Bf = Bfrag + cur * bufstride;
#pragma unroll
        for (int ks = 0; ks < 2; ks++) {
            int a[4][4], b[4][2];
#pragma unroll
            for (int i = 0; i < 4; i++) {
                a[i][0] = Af[i * 16 * SMS + ks * 8];
                a[i][1] = Af[i * 16 * SMS + 8 * SMS + ks * 8];
                a[i][2] = Af[i * 16 * SMS + ks * 8 + 4];
                a[i][3] = Af[i * 16 * SMS + 8 * SMS + ks * 8 + 4];
            }
#pragma unroll
            for (int j = 0; j < 4; j++) {
                b[j][0] = Bf[j * 8 * SMS + ks * 8];
                b[j][1] = Bf[j * 8 * SMS + ks * 8 + 4];
            }
#pragma unroll
            for (int i = 0; i < 4; i++)
#pragma unroll
                for (int j = 0; j < 4; j++)
                    mma_i8(acc[i][j][0], acc[i][j][1], acc[i][j][2], acc[i][j][3],
                           a[i][0], a[i][1], a[i][2], a[i][3], b[j][0], b[j][1]);
        }
        __syncthreads();
    }

    // epilogue: scale and store (each acc reg pair -> float2)
    float sav0[4], sav8[4];
#pragma unroll
    for (int i = 0; i < 4; i++) {
        sav0[i] = sa[m0 + wm * 64 + i * 16 + lr];
        sav8[i] = sa[m0 + wm * 64 + i * 16 + lr + 8];
    }
    float2 sbv[4];
#pragma unroll
    for (int j = 0; j < 4; j++) {
        int n = n0 + wn * 32 + j * 8 + 2 * c;
        sbv[j].x = sb[n];
        sbv[j].y = sb[n + 1];
    }
#pragma unroll
    for (int i = 0; i < 4; i++) {
        int mrow0 = m0 + wm * 64 + i * 16 + lr;
#pragma unroll
        for (int j = 0; j < 4; j++) {
            int n = n0 + wn * 32 + j * 8 + 2 * c;
            float2 o;
            o.x = (float)acc[i][j][0] * sav0[i] * sbv[j].x;
            o.y = (float)acc[i][j][1] * sav0[i] * sbv[j].y;
            *(float2*)&Y[(size_t)mrow0 * N + n] = o;
            o.x = (float)acc[i][j][2] * sav8[i] * sbv[j].x;
            o.y = (float)acc[i][j][3] * sav8[i] * sbv[j].y;
            *(float2*)&Y[(size_t)(mrow0 + 8) * N + n] = o;
        }
    }
}

// ---------------------------------------------------------------------------
// RoPE in-place on [S][nh*128]: pairs (d, d+64) per head
// ---------------------------------------------------------------------------
__global__ void rope_kernel(float* __restrict__ x, const float* __restrict__ cosb,
                            const float* __restrict__ sinb, int nh) {
    int idx = blockIdx.x * blockDim.x + threadIdx.x;
    int total = SEQ * nh * 64;
    if (idx >= total) return;
    int d = idx & 63;
    int h = (idx >> 6) % nh;
    int t = idx / (nh * 64);
    float c = cosb[t * 128 + d];
    float s = sinb[t * 128 + d];
    float* p = x + (size_t)t * nh * 128 + h * 128 + d;
    float x1 = p[0], x2 = p[64];
    p[0]  = x1 * c - x2 * s;
    p[64] = x2 * c + x1 * s;
}

// ---------------------------------------------------------------------------
// Causal GQA flash attention, fp32 online softmax.
// Grid: (qblock=32, head=32). Block: 512 threads (16 warps).
// Each warp owns 4 q rows; 64x64 KV tile staged in 64KB dynamic smem.
// ---------------------------------------------------------------------------
#define UPD(mi, li, a, s)                                      \
    {                                                          \
        float mn = fmaxf(mi, s);                               \
        float f = __expf(mi - mn);                             \
        float p = __expf(s - mn);                              \
        li = li * f + p;                                       \
        a.x = a.x * f + p * v4.x;                              \
        a.y = a.y * f + p * v4.y;                              \
        a.z = a.z * f + p * v4.z;                              \
        a.w = a.w * f + p * v4.w;                              \
        mi = mn;                                               \
    }

__global__ void attn_kernel() {
    extern __shared__ float sh[];
    float* Ks = sh;
    float* Vs = sh + 64 * 128;

    const int qb = blockIdx.x;
    const int h = blockIdx.y;
    const int kvh = h >> 2;
    const int tid = threadIdx.x;
    const int w = tid >> 5;
    const int lane = tid & 31;
    const int m0 = qb * 64 + w * 4;
    const int col = h * 128 + lane * 4;

    float4 qr0 = *(const float4*)&g_q[(size_t)(m0 + 0) * (NH * HD) + col];
    float4 qr1 = *(const float4*)&g_q[(size_t)(m0 + 1) * (NH * HD) + col];
    float4 qr2 = *(const float4*)&g_q[(size_t)(m0 + 2) * (NH * HD) + col];
    float4 qr3 = *(const float4*)&g_q[(size_t)(m0 + 3) * (NH * HD) + col];

    float mi0 = -CUDART_INF_F, mi1 = -CUDART_INF_F, mi2 = -CUDART_INF_F, mi3 = -CUDART_INF_F;
    float li0 = 0.f, li1 = 0.f, li2 = 0.f, li3 = 0.f;
    float4 a0 = {0, 0, 0, 0}, a1 = {0, 0, 0, 0}, a2 = {0, 0, 0, 0}, a3 = {0, 0, 0, 0};

    for (int kt = 0; kt <= qb; kt++) {
        __syncthreads();
#pragma unroll
        for (int l = 0; l < 4; l++) {
            int f = tid + 512 * l;          // float4 index within 64x32
            int j = f >> 5;
            int c = (f & 31) << 2;
            size_t g = (size_t)(kt * 64 + j) * (NKV * HD) + (size_t)kvh * HD + c;
            *(float4*)&Ks[j * 128 + c] = *(const float4*)&g_k[g];
            *(float4*)&Vs[j * 128 + c] = *(const float4*)&g_v[g];
        }
        __syncthreads();

        const bool diag = (kt == qb);
#pragma unroll 1
        for (int j = 0; j < 64; j++) {
            int key = kt * 64 + j;
            if (diag && key > m0 + 3) break;

            float4 k4 = *(const float4*)&Ks[j * 128 + lane * 4];
            float p0 = qr0.x * k4.x + qr0.y * k4.y + qr0.z * k4.z + qr0.w * k4.w;
            float p1 = qr1.x * k4.x + qr1.y * k4.y + qr1.z * k4.z + qr1.w * k4.w;
            float p2 = qr2.x * k4.x + qr2.y * k4.y + qr2.z * k4.z + qr2.w * k4.w;
            float p3 = qr3.x * k4.x + qr3.y * k4.y + qr3.z * k4.z + qr3.w * k4.w;
#pragma unroll
            for (int off = 16; off; off >>= 1) {
                p0 += __shfl_xor_sync(0xffffffffu, p0, off);
                p1 += __shfl_xor_sync(0xffffffffu, p1, off);
                p2 += __shfl_xor_sync(0xffffffffu, p2, off);
                p3 += __shfl_xor_sync(0xffffffffu, p3, off);
            }
            float4 v4 = *(const float4*)&Vs[j * 128 + lane * 4];
            p0 *= SCALE; p1 *= SCALE; p2 *= SCALE; p3 *= SCALE;

            if (!diag || key <= m0 + 0) UPD(mi0, li0, a0, p0);
            if (!diag || key <= m0 + 1) UPD(mi1, li1, a1, p1);
            if (!diag || key <= m0 + 2) UPD(mi2, li2, a2, p2);
            if (!diag || key <= m0 + 3) UPD(mi3, li3, a3, p3);
        }
    }

    float4 o;
    o.x = a0.x / li0; o.y = a0.y / li0; o.z = a0.z / li0; o.w = a0.w / li0;
    *(float4*)&g_attn[(size_t)(m0 + 0) * (NH * HD) + col] = o;
    o.x = a1.x / li1; o.y = a1.y / li1; o.z = a1.z / li1; o.w = a1.w / li1;
    *(float4*)&g_attn[(size_t)(m0 + 1) * (NH * HD) + col] = o;
    o.x = a2.x / li2; o.y = a2.y / li2; o.z = a2.z / li2; o.w = a2.w / li2;
    *(float4*)&g_attn[(size_t)(m0 + 2) * (NH * HD) + col] = o;
    o.x = a3.x / li3; o.y = a3.y / li3; o.z = a3.z / li3; o.w = a3.w / li3;
    *(float4*)&g_attn[(size_t)(m0 + 3) * (NH * HD) + col] = o;
}

// ---------------------------------------------------------------------------
// Host launch
// ---------------------------------------------------------------------------
extern "C" void kernel_launch(void* const* d_in, const int* in_sizes, int n_in,
                              void* d_out, int out_size) {
    (void)in_sizes; (void)n_in; (void)out_size;
    const float* hx   = (const float*)d_in[0];
    const float* cosb = (const float*)d_in[1];
    const float* sinb = (const float*)d_in[2];
    const float* Wq   = (const float*)d_in[3];
    const float* Wk   = (const float*)d_in[4];
    const float* Wv   = (const float*)d_in[5];
    const float* Wo   = (const float*)d_in[6];
    float* out = (float*)d_out;

    void *p_xq, *p_sx, *p_wq, *p_swq, *p_wk, *p_swk, *p_wv, *p_swv, *p_wo, *p_swo;
    void *p_q, *p_k, *p_v, *p_attn, *p_aq, *p_sa;
    cudaGetSymbolAddress(&p_xq, g_xq);   cudaGetSymbolAddress(&p_sx, g_sx);
    cudaGetSymbolAddress(&p_wq, g_wq);   cudaGetSymbolAddress(&p_swq, g_swq);
    cudaGetSymbolAddress(&p_wk, g_wk);   cudaGetSymbolAddress(&p_swk, g_swk);
    cudaGetSymbolAddress(&p_wv, g_wv);   cudaGetSymbolAddress(&p_swv, g_swv);
    cudaGetSymbolAddress(&p_wo, g_wo);   cudaGetSymbolAddress(&p_swo, g_swo);
    cudaGetSymbolAddress(&p_q, g_q);     cudaGetSymbolAddress(&p_k, g_k);
    cudaGetSymbolAddress(&p_v, g_v);     cudaGetSymbolAddress(&p_attn, g_attn);
    cudaGetSymbolAddress(&p_aq, g_aq);   cudaGetSymbolAddress(&p_sa, g_sa);

    // 1. fake-quant activations and weights (per-row int8 + scale)
    quant_rows_kernel<<<SEQ, 256>>>(hx, (int*)p_xq, (float*)p_sx);
    quant_rows_kernel<<<NH * HD, 256>>>(Wq, (int*)p_wq, (float*)p_swq);
    quant_rows_kernel<<<NKV * HD, 256>>>(Wk, (int*)p_wk, (float*)p_swk);
    quant_rows_kernel<<<NKV * HD, 256>>>(Wv, (int*)p_wv, (float*)p_swv);
    quant_rows_kernel<<<HDIM, 256>>>(Wo, (int*)p_wo, (float*)p_swo);

    // 2. QKV projections (exact int8 tensor-core GEMM, scaled epilogue)
    gemm_i8mma_kernel<<<dim3((NH * HD) / 128, SEQ / 128), 256>>>(
        (const int*)p_xq, (const float*)p_sx, (const int*)p_wq, (const float*)p_swq,
        (float*)p_q, NH * HD);
    gemm_i8mma_kernel<<<dim3((NKV * HD) / 128, SEQ / 128), 256>>>(
        (const int*)p_xq, (const float*)p_sx, (const int*)p_wk, (const float*)p_swk,
        (float*)p_k, NKV * HD);
    gemm_i8mma_kernel<<<dim3((NKV * HD) / 128, SEQ / 128), 256>>>(
        (const int*)p_xq, (const float*)p_sx, (const int*)p_wv, (const float*)p_swv,
        (float*)p_v, NKV * HD);

    // 3. RoPE
    rope_kernel<<<(SEQ * NH * 64 + 255) / 256, 256>>>((float*)p_q, cosb, sinb, NH);
    rope_kernel<<<(SEQ * NKV * 64 + 255) / 256, 256>>>((float*)p_k, cosb, sinb, NKV);

    // 4. causal GQA flash attention
    cudaFuncSetAttribute(attn_kernel, cudaFuncAttributeMaxDynamicSharedMemorySize, 65536);
    attn_kernel<<<dim3(SEQ / 64, NH), 512, 65536>>>();

    // 5. fake-quant attention output, then O projection into d_out
    quant_rows_kernel<<<SEQ, 256>>>((const float*)p_attn, (int*)p_aq, (float*)p_sa);
    gemm_i8mma_kernel<<<dim3(HDIM / 128, SEQ / 128), 256>>>(
        (const int*)p_aq, (const float*)p_sa, (const int*)p_wo, (const float*)p_swo,
        out, HDIM);
}

// round 3
// speedup vs baseline: 3.5772x; 2.8990x over previous
#include <cuda_runtime.h>
#include <math_constants.h>
#include <cstdint>

#define SEQ   2048
#define HDIM  4096
#define NH    32
#define NKV   8
#define HD    128
#define KINT  1024          // HDIM / 4 bytes packed per int
#define SCALE 0.08838834764831845f   // 1/sqrt(128)

// ---------------------------------------------------------------------------
// Scratch (static device globals; no runtime allocation)
// ---------------------------------------------------------------------------
__device__ int   g_xq[SEQ * KINT];          // quantized hidden (int8 packed)
__device__ float g_sx[SEQ];
__device__ int   g_wq[(NH * HD) * KINT];
__device__ float g_swq[NH * HD];
__device__ int   g_wk[(NKV * HD) * KINT];
__device__ float g_swk[NKV * HD];
__device__ int   g_wv[(NKV * HD) * KINT];
__device__ float g_swv[NKV * HD];
__device__ int   g_wo[HDIM * KINT];
__device__ float g_swo[HDIM];
__device__ float g_q[SEQ * NH * HD];
__device__ float g_k[SEQ * NKV * HD];
__device__ float g_v[SEQ * NKV * HD];
__device__ float g_attn[SEQ * NH * HD];
__device__ int   g_aq[SEQ * KINT];
__device__ float g_sa[SEQ];

// ---------------------------------------------------------------------------
// Per-row fake-quant: amax/127 scale, round-half-even, pack 4x int8 into int.
// ---------------------------------------------------------------------------
__global__ void quant_rows_kernel(const float* __restrict__ in,
                                  int* __restrict__ outp,
                                  float* __restrict__ scales) {
    const int row = blockIdx.x;
    const int t = threadIdx.x;
    const float4* inr = (const float4*)(in + (size_t)row * HDIM);

    float4 v[4];
    float amax = 0.f;
#pragma unroll
    for (int l = 0; l < 4; l++) {
        v[l] = inr[t + 256 * l];
        amax = fmaxf(amax, fmaxf(fmaxf(fabsf(v[l].x), fabsf(v[l].y)),
                                 fmaxf(fabsf(v[l].z), fabsf(v[l].w))));
    }
    __shared__ float red[256];
    red[t] = amax;
    __syncthreads();
#pragma unroll
    for (int st = 128; st > 0; st >>= 1) {
        if (t < st) red[t] = fmaxf(red[t], red[t + st]);
        __syncthreads();
    }
    float s = __fdiv_rn(red[0], 127.0f);
    s = fmaxf(s, 1e-8f);
    if (t == 0) scales[row] = s;

#pragma unroll
    for (int l = 0; l < 4; l++) {
        float4 x = v[l];
        int a = (int)fminf(fmaxf(rintf(__fdiv_rn(x.x, s)), -128.f), 127.f);
        int b = (int)fminf(fmaxf(rintf(__fdiv_rn(x.y, s)), -128.f), 127.f);
        int c = (int)fminf(fmaxf(rintf(__fdiv_rn(x.z, s)), -128.f), 127.f);
        int d = (int)fminf(fmaxf(rintf(__fdiv_rn(x.w, s)), -128.f), 127.f);
        int p = (a & 0xFF) | ((b & 0xFF) << 8) | ((c & 0xFF) << 16) | (d << 24);
        outp[(size_t)row * KINT + t + 256 * l] = p;
    }
}

// ---------------------------------------------------------------------------
// Int8 tensor-core GEMM (exact): 128x128 tiles, cp.async double buffer
// ---------------------------------------------------------------------------
#define SMS 20   // smem row stride in ints

__device__ __forceinline__ void cp_async16(void* smem, const void* g) {
    uint32_t s = (uint32_t)__cvta_generic_to_shared(smem);
    asm volatile("cp.async.cg.shared.global [%0], [%1], 16;\n" :: "r"(s), "l"(g));
}

__device__ __forceinline__ void mma_i8(int& c0, int& c1, int& c2, int& c3,
                                       int a0, int a1, int a2, int a3,
                                       int b0, int b1) {
    asm volatile(
        "mma.sync.aligned.m16n8k32.row.col.s32.s8.s8.s32 "
        "{%0,%1,%2,%3}, {%4,%5,%6,%7}, {%8,%9}, {%0,%1,%2,%3};\n"
        : "+r"(c0), "+r"(c1), "+r"(c2), "+r"(c3)
        : "r"(a0), "r"(a1), "r"(a2), "r"(a3), "r"(b0), "r"(b1));
}

__global__ __launch_bounds__(256, 2)
void gemm_i8mma_kernel(const int* __restrict__ A, const float* __restrict__ sa,
                       const int* __restrict__ B, const float* __restrict__ sb,
                       float* __restrict__ Y, int N) {
    __shared__ int As[2][128 * SMS];
    __shared__ int Bs[2][128 * SMS];

    const int tid = threadIdx.x;
    const int warp = tid >> 5;
    const int lane = tid & 31;
    const int wm = warp >> 2;
    const int wn = warp & 3;
    const int lr = lane >> 2;
    const int c  = lane & 3;
    const int m0 = blockIdx.y * 128;
    const int n0 = blockIdx.x * 128;

    const int r0g = tid >> 2;
    const int ch  = tid & 3;

    const int* Ag0 = A + (size_t)(m0 + r0g) * KINT + ch * 4;
    const int* Ag1 = A + (size_t)(m0 + r0g + 64) * KINT + ch * 4;
    const int* Bg0 = B + (size_t)(n0 + r0g) * KINT + ch * 4;
    const int* Bg1 = B + (size_t)(n0 + r0g + 64) * KINT + ch * 4;
    int* As0 = &As[0][r0g * SMS + ch * 4];
    int* As1 = &As[0][(r0g + 64) * SMS + ch * 4];
    int* Bs0 = &Bs[0][r0g * SMS + ch * 4];
    int* Bs1 = &Bs[0][(r0g + 64) * SMS + ch * 4];
    const int bufstride = 128 * SMS;

    int acc[4][4][4] = {};

    cp_async16(As0, Ag0);
    cp_async16(As1, Ag1);
    cp_async16(Bs0, Bg0);
    cp_async16(Bs1, Bg1);
    asm volatile("cp.async.commit_group;\n");

    const int* Afrag = &As[0][(wm * 64 + lr) * SMS + c];
    const int* Bfrag = &Bs[0][(wn * 32 + lr) * SMS + c];

    for (int it = 0; it < 64; it++) {
        int cur = it & 1;
        if (it < 63) {
            int nb = (it + 1) & 1;
            int ko = (it + 1) * 16;
            cp_async16(As0 + nb * bufstride, Ag0 + ko);
            cp_async16(As1 + nb * bufstride, Ag1 + ko);
            cp_async16(Bs0 + nb * bufstride, Bg0 + ko);
            cp_async16(Bs1 + nb * bufstride, Bg1 + ko);
            asm volatile("cp.async.commit_group;\n");
            asm volatile("cp.async.wait_group 1;\n");
        } else {
            asm volatile("cp.async.wait_group 0;\n");
        }
        __syncthreads();

        const int* Af = Afrag + cur * bufstride;
        const int* Bf = Bfrag + cur * bufstride;
#pragma unroll
        for (int ks = 0; ks < 2; ks++) {
            int a[4][4], b[4][2];
#pragma unroll
            for (int i = 0; i < 4; i++) {
                a[i][0] = Af[i * 16 * SMS + ks * 8];
                a[i][1] = Af[i * 16 * SMS + 8 * SMS + ks * 8];
                a[i][2] = Af[i * 16 * SMS + ks * 8 + 4];
                a[i][3] = Af[i * 16 * SMS + 8 * SMS + ks * 8 + 4];
            }
#pragma unroll
            for (int j = 0; j < 4; j++) {
                b[j][0] = Bf[j * 8 * SMS + ks * 8];
                b[j][1] = Bf[j * 8 * SMS + ks * 8 + 4];
            }
#pragma unroll
            for (int i = 0; i < 4; i++)
#pragma unroll
                for (int j = 0; j < 4; j++)
                    mma_i8(acc[i][j][0], acc[i][j][1], acc[i][j][2], acc[i][j][3],
                           a[i][0], a[i][1], a[i][2], a[i][3], b[j][0], b[j][1]);
        }
        __syncthreads();
    }

    float sav0[4], sav8[4];
#pragma unroll
    for (int i = 0; i < 4; i++) {
        sav0[i] = sa[m0 + wm * 64 + i * 16 + lr];
        sav8[i] = sa[m0 + wm * 64 + i * 16 + lr + 8];
    }
    float2 sbv[4];
#pragma unroll
    for (int j = 0; j < 4; j++) {
        int n = n0 + wn * 32 + j * 8 + 2 * c;
        sbv[j].x = sb[n];
        sbv[j].y = sb[n + 1];
    }
#pragma unroll
    for (int i = 0; i < 4; i++) {
        int mrow0 = m0 + wm * 64 + i * 16 + lr;
#pragma unroll
        for (int j = 0; j < 4; j++) {
            int n = n0 + wn * 32 + j * 8 + 2 * c;
            float2 o;
            o.x = (float)acc[i][j][0] * sav0[i] * sbv[j].x;
            o.y = (float)acc[i][j][1] * sav0[i] * sbv[j].y;
            *(float2*)&Y[(size_t)mrow0 * N + n] = o;
            o.x = (float)acc[i][j][2] * sav8[i] * sbv[j].x;
            o.y = (float)acc[i][j][3] * sav8[i] * sbv[j].y;
            *(float2*)&Y[(size_t)(mrow0 + 8) * N + n] = o;
        }
    }
}

// ---------------------------------------------------------------------------
// RoPE in-place on [S][nh*128]: pairs (d, d+64) per head
// ---------------------------------------------------------------------------
__global__ void rope_kernel(float* __restrict__ x, const float* __restrict__ cosb,
                            const float* __restrict__ sinb, int nh) {
    int idx = blockIdx.x * blockDim.x + threadIdx.x;
    int total = SEQ * nh * 64;
    if (idx >= total) return;
    int d = idx & 63;
    int h = (idx >> 6) % nh;
    int t = idx / (nh * 64);
    float c = cosb[t * 128 + d];
    float s = sinb[t * 128 + d];
    float* p = x + (size_t)t * nh * 128 + h * 128 + d;
    float x1 = p[0], x2 = p[64];
    p[0]  = x1 * c - x2 * s;
    p[64] = x2 * c + x1 * s;
}

// ---------------------------------------------------------------------------
// Causal GQA flash attention v2: register-tiled GEMMs, tile-level softmax.
// Grid (32 qblocks, 32 heads), 256 threads. Thread (tm,tn) owns q rows
// tm*4..+3; GEMM1 keys tn+16j (interleaved, bank-friendly); GEMM2 d-cols
// tn*4..+3 and 64+tn*4..+3. K/V cp.async double-buffered; one expf/element.
// ---------------------------------------------------------------------------
#define AST 132          // Q/K/V smem row stride (floats)
#define PST 68           // P smem row stride

__global__ __launch_bounds__(256, 1) void attn2_kernel() {
    extern __shared__ float sh[];
    float* Qs = sh;                       // 64*AST
    float* Ks = Qs + 64 * AST;            // 2 buffers
    float* Vs = Ks + 2 * 64 * AST;        // 2 buffers
    float* Ps = Vs + 2 * 64 * AST;        // 64*PST

    const int qb = blockIdx.x;
    const int h = blockIdx.y;
    const int kvh = h >> 2;
    const int tid = threadIdx.x;
    const int tm = tid >> 4;
    const int tn = tid & 15;
    const int m0 = qb * 64;

    // stage Q tile (post-RoPE) + K/V tile 0
#pragma unroll
    for (int t = 0; t < 8; t++) {
        int cid = tid + t * 256;
        int row = cid >> 5, ch = cid & 31;
        cp_async16(&Qs[row * AST + ch * 4],
                   g_q + (size_t)(m0 + row) * (NH * HD) + h * HD + ch * 4);
    }
#pragma unroll
    for (int t = 0; t < 8; t++) {
        int cid = tid + t * 256;
        int row = cid >> 5, ch = cid & 31;
        size_t src = (size_t)row * (NKV * HD) + (size_t)kvh * HD + ch * 4;
        cp_async16(&Ks[row * AST + ch * 4], g_k + src);
        cp_async16(&Vs[row * AST + ch * 4], g_v + src);
    }
    asm volatile("cp.async.commit_group;\n");

    float mi[4] = {-1e30f, -1e30f, -1e30f, -1e30f};
    float li[4] = {0.f, 0.f, 0.f, 0.f};
    float4 acc0[4] = {{0,0,0,0},{0,0,0,0},{0,0,0,0},{0,0,0,0}};
    float4 acc1[4] = {{0,0,0,0},{0,0,0,0},{0,0,0,0},{0,0,0,0}};

    for (int kt = 0; kt <= qb; kt++) {
        const int cur = kt & 1;
        if (kt < qb) {
            const int nb = cur ^ 1;
#pragma unroll
            for (int t = 0; t < 8; t++) {
                int cid = tid + t * 256;
                int row = cid >> 5, ch = cid & 31;
                size_t src = (size_t)((kt + 1) * 64 + row) * (NKV * HD) +
                             (size_t)kvh * HD + ch * 4;
                cp_async16(&Ks[nb * 64 * AST + row * AST + ch * 4], g_k + src);
                cp_async16(&Vs[nb * 64 * AST + row * AST + ch * 4], g_v + src);
            }
            asm volatile("cp.async.commit_group;\n");
            asm volatile("cp.async.wait_group 1;\n");
        } else {
            asm volatile("cp.async.wait_group 0;\n");
        }
        __syncthreads();

        const float* Kb = Ks + cur * 64 * AST;
        const float* Vb = Vs + cur * 64 * AST;

        // ---- GEMM1: S[4q][4k] over d=128 ----
        float S[4][4] = {};
#pragma unroll 4
        for (int d = 0; d < 128; d += 4) {
            float4 qf[4], kf[4];
#pragma unroll
            for (int i = 0; i < 4; i++)
                qf[i] = *(const float4*)&Qs[(tm * 4 + i) * AST + d];
#pragma unroll
            for (int j = 0; j < 4; j++)
                kf[j] = *(const float4*)&Kb[(tn + 16 * j) * AST + d];
#pragma unroll
            for (int i = 0; i < 4; i++)
#pragma unroll
                for (int j = 0; j < 4; j++) {
                    S[i][j] += qf[i].x * kf[j].x;
                    S[i][j] += qf[i].y * kf[j].y;
                    S[i][j] += qf[i].z * kf[j].z;
                    S[i][j] += qf[i].w * kf[j].w;
                }
        }
#pragma unroll
        for (int i = 0; i < 4; i++)
#pragma unroll
            for (int j = 0; j < 4; j++)
                S[i][j] *= SCALE;

        if (kt == qb) {
#pragma unroll
            for (int i = 0; i < 4; i++)
#pragma unroll
                for (int j = 0; j < 4; j++)
                    if (tn + 16 * j > tm * 4 + i) S[i][j] = -1e30f;
        }

        // ---- tile softmax (online) ----
        float scl[4];
#pragma unroll
        for (int i = 0; i < 4; i++) {
            float t = fmaxf(fmaxf(S[i][0], S[i][1]), fmaxf(S[i][2], S[i][3]));
#pragma unroll
            for (int off = 1; off < 16; off <<= 1)
                t = fmaxf(t, __shfl_xor_sync(0xffffffffu, t, off));
            float nm = fmaxf(mi[i], t);
            scl[i] = __expf(mi[i] - nm);
            mi[i] = nm;
            float p0 = __expf(S[i][0] - nm);
            float p1 = __expf(S[i][1] - nm);
            float p2 = __expf(S[i][2] - nm);
            float p3 = __expf(S[i][3] - nm);
            float rs = (p0 + p1) + (p2 + p3);
#pragma unroll
            for (int off = 1; off < 16; off <<= 1)
                rs += __shfl_xor_sync(0xffffffffu, rs, off);
            li[i] = li[i] * scl[i] + rs;
            float* pr = &Ps[(tm * 4 + i) * PST];
            pr[tn]      = p0;
            pr[tn + 16] = p1;
            pr[tn + 32] = p2;
            pr[tn + 48] = p3;
        }
        __syncthreads();

        // rescale accumulators
#pragma unroll
        for (int i = 0; i < 4; i++) {
            acc0[i].x *= scl[i]; acc0[i].y *= scl[i];
            acc0[i].z *= scl[i]; acc0[i].w *= scl[i];
            acc1[i].x *= scl[i]; acc1[i].y *= scl[i];
            acc1[i].z *= scl[i]; acc1[i].w *= scl[i];
        }

        // ---- GEMM2: acc[4q][8d] += P[4q][64k] x V[64k][8d] ----
#pragma unroll 2
        for (int k = 0; k < 64; k++) {
            float4 v0 = *(const float4*)&Vb[k * AST + tn * 4];
            float4 v1 = *(const float4*)&Vb[k * AST + 64 + tn * 4];
#pragma unroll
            for (int i = 0; i < 4; i++) {
                float p = Ps[(tm * 4 + i) * PST + k];
                acc0[i].x += p * v0.x; acc0[i].y += p * v0.y;
                acc0[i].z += p * v0.z; acc0[i].w += p * v0.w;
                acc1[i].x += p * v1.x; acc1[i].y += p * v1.y;
                acc1[i].z += p * v1.z; acc1[i].w += p * v1.w;
            }
        }
        __syncthreads();
    }

#pragma unroll
    for (int i = 0; i < 4; i++) {
        float inv = __fdiv_rn(1.0f, li[i]);
        float4 o;
        o.x = acc0[i].x * inv; o.y = acc0[i].y * inv;
        o.z = acc0[i].z * inv; o.w = acc0[i].w * inv;
        float* dst = &g_attn[(size_t)(m0 + tm * 4 + i) * (NH * HD) + h * HD];
        *(float4*)&dst[tn * 4] = o;
        o.x = acc1[i].x * inv; o.y = acc1[i].y * inv;
        o.z = acc1[i].z * inv; o.w = acc1[i].w * inv;
        *(float4*)&dst[64 + tn * 4] = o;
    }
}

#define ATTN_SMEM ((64 * AST + 4 * 64 * AST + 64 * PST) * 4)

// ---------------------------------------------------------------------------
// Host launch
// ---------------------------------------------------------------------------
extern "C" void kernel_launch(void* const* d_in, const int* in_sizes, int n_in,
                              void* d_out, int out_size) {
    (void)in_sizes; (void)n_in; (void)out_size;
    const float* hx   = (const float*)d_in[0];
    const float* cosb = (const float*)d_in[1];
    const float* sinb = (const float*)d_in[2];
    const float* Wq   = (const float*)d_in[3];
    const float* Wk   = (const float*)d_in[4];
    const float* Wv   = (const float*)d_in[5];
    const float* Wo   = (const float*)d_in[6];
    float* out = (float*)d_out;

    void *p_xq, *p_sx, *p_wq, *p_swq, *p_wk, *p_swk, *p_wv, *p_swv, *p_wo, *p_swo;
    void *p_q, *p_k, *p_v, *p_attn, *p_aq, *p_sa;
    cudaGetSymbolAddress(&p_xq, g_xq);   cudaGetSymbolAddress(&p_sx, g_sx);
    cudaGetSymbolAddress(&p_wq, g_wq);   cudaGetSymbolAddress(&p_swq, g_swq);
    cudaGetSymbolAddress(&p_wk, g_wk);   cudaGetSymbolAddress(&p_swk, g_swk);
    cudaGetSymbolAddress(&p_wv, g_wv);   cudaGetSymbolAddress(&p_swv, g_swv);
    cudaGetSymbolAddress(&p_wo, g_wo);   cudaGetSymbolAddress(&p_swo, g_swo);
    cudaGetSymbolAddress(&p_q, g_q);     cudaGetSymbolAddress(&p_k, g_k);
    cudaGetSymbolAddress(&p_v, g_v);     cudaGetSymbolAddress(&p_attn, g_attn);
    cudaGetSymbolAddress(&p_aq, g_aq);   cudaGetSymbolAddress(&p_sa, g_sa);

    // 1. fake-quant activations and weights
    quant_rows_kernel<<<SEQ, 256>>>(hx, (int*)p_xq, (float*)p_sx);
    quant_rows_kernel<<<NH * HD, 256>>>(Wq, (int*)p_wq, (float*)p_swq);
    quant_rows_kernel<<<NKV * HD, 256>>>(Wk, (int*)p_wk, (float*)p_swk);
    quant_rows_kernel<<<NKV * HD, 256>>>(Wv, (int*)p_wv, (float*)p_swv);
    quant_rows_kernel<<<HDIM, 256>>>(Wo, (int*)p_wo, (float*)p_swo);

    // 2. QKV projections (exact int8 tensor-core GEMM)
    gemm_i8mma_kernel<<<dim3((NH * HD) / 128, SEQ / 128), 256>>>(
        (const int*)p_xq, (const float*)p_sx, (const int*)p_wq, (const float*)p_swq,
        (float*)p_q, NH * HD);
    gemm_i8mma_kernel<<<dim3((NKV * HD) / 128, SEQ / 128), 256>>>(
        (const int*)p_xq, (const float*)p_sx, (const int*)p_wk, (const float*)p_swk,
        (float*)p_k, NKV * HD);
    gemm_i8mma_kernel<<<dim3((NKV * HD) / 128, SEQ / 128), 256>>>(
        (const int*)p_xq, (const float*)p_sx, (const int*)p_wv, (const float*)p_swv,
        (float*)p_v, NKV * HD);

    // 3. RoPE
    rope_kernel<<<(SEQ * NH * 64 + 255) / 256, 256>>>((float*)p_q, cosb, sinb, NH);
    rope_kernel<<<(SEQ * NKV * 64 + 255) / 256, 256>>>((float*)p_k, cosb, sinb, NKV);

    // 4. causal GQA flash attention v2
    cudaFuncSetAttribute(attn2_kernel, cudaFuncAttributeMaxDynamicSharedMemorySize,
                         ATTN_SMEM);
    attn2_kernel<<<dim3(SEQ / 64, NH), 256, ATTN_SMEM>>>();

    // 5. fake-quant attention output, then O projection into d_out
    quant_rows_kernel<<<SEQ, 256>>>((const float*)p_attn, (int*)p_aq, (float*)p_sa);
    gemm_i8mma_kernel<<<dim3(HDIM / 128, SEQ / 128), 256>>>(
        (const int*)p_aq, (const float*)p_sa, (const int*)p_wo, (const float*)p_swo,
        out, HDIM);
}

// round 5
// speedup vs baseline: 3.9187x; 1.0955x over previous
#include <cuda_runtime.h>
#include <math_constants.h>
#include <cstdint>

#define SEQ   2048
#define HDIM  4096
#define NH    32
#define NKV   8
#define HD    128
#define KINT  1024          // HDIM / 4 bytes packed per int
#define SCALE 0.08838834764831845f   // 1/sqrt(128)

// ---------------------------------------------------------------------------
// Scratch (static device globals; no runtime allocation)
// ---------------------------------------------------------------------------
__device__ int   g_xq[SEQ * KINT];          // quantized hidden (int8 packed)
__device__ float g_sx[SEQ];
__device__ int   g_wq[(NH * HD) * KINT];
__device__ float g_swq[NH * HD];
__device__ int   g_wk[(NKV * HD) * KINT];
__device__ float g_swk[NKV * HD];
__device__ int   g_wv[(NKV * HD) * KINT];
__device__ float g_swv[NKV * HD];
__device__ int   g_wo[HDIM * KINT];
__device__ float g_swo[HDIM];
__device__ float g_q[SEQ * NH * HD];
__device__ float g_k[SEQ * NKV * HD];
__device__ float g_v[SEQ * NKV * HD];
__device__ float g_attn[SEQ * NH * HD];
__device__ int   g_aq[SEQ * KINT];
__device__ float g_sa[SEQ];

// ---------------------------------------------------------------------------
// Per-row fake-quant: amax/127 scale, round-half-even, pack 4x int8 into int.
// ---------------------------------------------------------------------------
__global__ void quant_rows_kernel(const float* __restrict__ in,
                                  int* __restrict__ outp,
                                  float* __restrict__ scales) {
    const int row = blockIdx.x;
    const int t = threadIdx.x;
    const float4* inr = (const float4*)(in + (size_t)row * HDIM);

    float4 v[4];
    float amax = 0.f;
#pragma unroll
    for (int l = 0; l < 4; l++) {
        v[l] = inr[t + 256 * l];
        amax = fmaxf(amax, fmaxf(fmaxf(fabsf(v[l].x), fabsf(v[l].y)),
                                 fmaxf(fabsf(v[l].z), fabsf(v[l].w))));
    }
    __shared__ float red[256];
    red[t] = amax;
    __syncthreads();
#pragma unroll
    for (int st = 128; st > 0; st >>= 1) {
        if (t < st) red[t] = fmaxf(red[t], red[t + st]);
        __syncthreads();
    }
    float s = __fdiv_rn(red[0], 127.0f);
    s = fmaxf(s, 1e-8f);
    if (t == 0) scales[row] = s;

#pragma unroll
    for (int l = 0; l < 4; l++) {
        float4 x = v[l];
        int a = (int)fminf(fmaxf(rintf(__fdiv_rn(x.x, s)), -128.f), 127.f);
        int b = (int)fminf(fmaxf(rintf(__fdiv_rn(x.y, s)), -128.f), 127.f);
        int c = (int)fminf(fmaxf(rintf(__fdiv_rn(x.z, s)), -128.f), 127.f);
        int d = (int)fminf(fmaxf(rintf(__fdiv_rn(x.w, s)), -128.f), 127.f);
        int p = (a & 0xFF) | ((b & 0xFF) << 8) | ((c & 0xFF) << 16) | (d << 24);
        outp[(size_t)row * KINT + t + 256 * l] = p;
    }
}

// ---------------------------------------------------------------------------
// Int8 tensor-core GEMM (exact): 128x128 tiles, BK=128 bytes (32 ints),
// cp.async double buffer in DYNAMIC shared memory (72KB), 32 iterations.
// blockIdx.z selects operand set (fused K/V projection in one launch).
// Smem row stride 36 ints: fragment LDS banks (lr*36 + c) mod 32 = 4*lr + c,
// a permutation over the warp -> conflict-free.
// ---------------------------------------------------------------------------
#define SMS2 36
#define GEMM_BUFSTRIDE (128 * SMS2)
#define GEMM_SMEM (2 * 2 * GEMM_BUFSTRIDE * 4)   // 73728 bytes

__device__ __forceinline__ void cp_async16(void* smem, const void* g) {
    uint32_t s = (uint32_t)__cvta_generic_to_shared(smem);
    asm volatile("cp.async.cg.shared.global [%0], [%1], 16;\n" :: "r"(s), "l"(g));
}

__device__ __forceinline__ void mma_i8(int& c0, int& c1, int& c2, int& c3,
                                       int a0, int a1, int a2, int a3,
                                       int b0, int b1) {
    asm volatile(
        "mma.sync.aligned.m16n8k32.row.col.s32.s8.s8.s32 "
        "{%0,%1,%2,%3}, {%4,%5,%6,%7}, {%8,%9}, {%0,%1,%2,%3};\n"
        : "+r"(c0), "+r"(c1), "+r"(c2), "+r"(c3)
        : "r"(a0), "r"(a1), "r"(a2), "r"(a3), "r"(b0), "r"(b1));
}

__global__ __launch_bounds__(256, 2)
void gemm_i8mma_kernel(const int* __restrict__ A, const float* __restrict__ sa,
                       const int* __restrict__ B0, const float* __restrict__ sb0,
                       float* __restrict__ Y0,
                       const int* __restrict__ B1, const float* __restrict__ sb1,
                       float* __restrict__ Y1, int N) {
    const int* __restrict__ B = blockIdx.z ? B1 : B0;
    const float* __restrict__ sb = blockIdx.z ? sb1 : sb0;
    float* __restrict__ Y = blockIdx.z ? Y1 : Y0;

    extern __shared__ int dynsmem[];
    int* As = dynsmem;                        // 2 buffers of 128*SMS2
    int* Bs = dynsmem + 2 * GEMM_BUFSTRIDE;   // 2 buffers of 128*SMS2

    const int tid = threadIdx.x;
    const int warp = tid >> 5;
    const int lane = tid & 31;
    const int wm = warp >> 2;
    const int wn = warp & 3;
    const int lr = lane >> 2;
    const int c  = lane & 3;
    const int m0 = blockIdx.y * 128;
    const int n0 = blockIdx.x * 128;

    // global->smem: 128 rows x 8 chunks of 16B per operand; 4 rows per thread
    const int r0 = tid >> 3;            // 0..31
    const int ch = tid & 7;             // 16B chunk in 128B k-slab

    const int* Ag[4];
    const int* Bg[4];
    int* Asw[4];
    int* Bsw[4];
#pragma unroll
    for (int rr = 0; rr < 4; rr++) {
        int row = r0 + 32 * rr;
        Ag[rr] = A + (size_t)(m0 + row) * KINT + ch * 4;
        Bg[rr] = B + (size_t)(n0 + row) * KINT + ch * 4;
        Asw[rr] = &As[row * SMS2 + ch * 4];
        Bsw[rr] = &Bs[row * SMS2 + ch * 4];
    }

    int acc[4][4][4] = {};

    // prologue: k-chunk 0
#pragma unroll
    for (int rr = 0; rr < 4; rr++) {
        cp_async16(Asw[rr], Ag[rr]);
        cp_async16(Bsw[rr], Bg[rr]);
    }
    asm volatile("cp.async.commit_group;\n");

    const int* Afrag = &As[(wm * 64 + lr) * SMS2 + c];
    const int* Bfrag = &Bs[(wn * 32 + lr) * SMS2 + c];

    for (int it = 0; it < 32; it++) {
        int cur = it & 1;
        if (it < 31) {
            int nb = (it + 1) & 1;
            int ko = (it + 1) * 32;
#pragma unroll
            for (int rr = 0; rr < 4; rr++) {
                cp_async16(Asw[rr] + nb * GEMM_BUFSTRIDE, Ag[rr] + ko);
                cp_async16(Bsw[rr] + nb * GEMM_BUFSTRIDE, Bg[rr] + ko);
            }
            asm volatile("cp.async.commit_group;\n");
            asm volatile("cp.async.wait_group 1;\n");
        } else {
            asm volatile("cp.async.wait_group 0;\n");
        }
        __syncthreads();

        const int* Af = Afrag + cur * GEMM_BUFSTRIDE;
        const int* Bf = Bfrag + cur * GEMM_BUFSTRIDE;
#pragma unroll
        for (int ks = 0; ks < 4; ks++) {
            int a[4][4], b[4][2];
#pragma unroll
            for (int i = 0; i < 4; i++) {
                a[i][0] = Af[i * 16 * SMS2 + ks * 8];
                a[i][1] = Af[i * 16 * SMS2 + 8 * SMS2 + ks * 8];
                a[i][2] = Af[i * 16 * SMS2 + ks * 8 + 4];
                a[i][3] = Af[i * 16 * SMS2 + 8 * SMS2 + ks * 8 + 4];
            }
#pragma unroll
            for (int j = 0; j < 4; j++) {
                b[j][0] = Bf[j * 8 * SMS2 + ks * 8];
                b[j][1] = Bf[j * 8 * SMS2 + ks * 8 + 4];
            }
#pragma unroll
            for (int i = 0; i < 4; i++)
#pragma unroll
                for (int j = 0; j < 4; j++)
                    mma_i8(acc[i][j][0], acc[i][j][1], acc[i][j][2], acc[i][j][3],
                           a[i][0], a[i][1], a[i][2], a[i][3], b[j][0], b[j][1]);
        }
        __syncthreads();
    }

    float sav0[4], sav8[4];
#pragma unroll
    for (int i = 0; i < 4; i++) {
        sav0[i] = sa[m0 + wm * 64 + i * 16 + lr];
        sav8[i] = sa[m0 + wm * 64 + i * 16 + lr + 8];
    }
    float2 sbv[4];
#pragma unroll
    for (int j = 0; j < 4; j++) {
        int n = n0 + wn * 32 + j * 8 + 2 * c;
        sbv[j].x = sb[n];
        sbv[j].y = sb[n + 1];
    }
#pragma unroll
    for (int i = 0; i < 4; i++) {
        int mrow0 = m0 + wm * 64 + i * 16 + lr;
#pragma unroll
        for (int j = 0; j < 4; j++) {
            int n = n0 + wn * 32 + j * 8 + 2 * c;
            float2 o;
            o.x = (float)acc[i][j][0] * sav0[i] * sbv[j].x;
            o.y = (float)acc[i][j][1] * sav0[i] * sbv[j].y;
            *(float2*)&Y[(size_t)mrow0 * N + n] = o;
            o.x = (float)acc[i][j][2] * sav8[i] * sbv[j].x;
            o.y = (float)acc[i][j][3] * sav8[i] * sbv[j].y;
            *(float2*)&Y[(size_t)(mrow0 + 8) * N + n] = o;
        }
    }
}

// ---------------------------------------------------------------------------
// RoPE in-place on [S][nh*128]: pairs (d, d+64) per head
// ---------------------------------------------------------------------------
__global__ void rope_kernel(float* __restrict__ x, const float* __restrict__ cosb,
                            const float* __restrict__ sinb, int nh) {
    int idx = blockIdx.x * blockDim.x + threadIdx.x;
    int total = SEQ * nh * 64;
    if (idx >= total) return;
    int d = idx & 63;
    int h = (idx >> 6) % nh;
    int t = idx / (nh * 64);
    float c = cosb[t * 128 + d];
    float s = sinb[t * 128 + d];
    float* p = x + (size_t)t * nh * 128 + h * 128 + d;
    float x1 = p[0], x2 = p[64];
    p[0]  = x1 * c - x2 * s;
    p[64] = x2 * c + x1 * s;
}

// ---------------------------------------------------------------------------
// Causal GQA flash attention v2: register-tiled GEMMs, tile-level softmax.
// 1D grid, heavy-first ordering: qb = 31 - (bid>>5) so the longest blocks
// (most KV tiles) are dispatched in wave 1 -> near-optimal greedy makespan.
// ---------------------------------------------------------------------------
#define AST 132          // Q/K/V smem row stride (floats)
#define PST 68           // P smem row stride

__global__ __launch_bounds__(256, 1) void attn2_kernel() {
    extern __shared__ float sh[];
    float* Qs = sh;                       // 64*AST
    float* Ks = Qs + 64 * AST;            // 2 buffers
    float* Vs = Ks + 2 * 64 * AST;        // 2 buffers
    float* Ps = Vs + 2 * 64 * AST;        // 64*PST

    const int bid = blockIdx.x;
    const int qb = 31 - (bid >> 5);       // heavy blocks first
    const int h = bid & 31;
    const int kvh = h >> 2;
    const int tid = threadIdx.x;
    const int tm = tid >> 4;
    const int tn = tid & 15;
    const int m0 = qb * 64;

    // stage Q tile (post-RoPE) + K/V tile 0
#pragma unroll
    for (int t = 0; t < 8; t++) {
        int cid = tid + t * 256;
        int row = cid >> 5, ch = cid & 31;
        cp_async16(&Qs[row * AST + ch * 4],
                   g_q + (size_t)(m0 + row) * (NH * HD) + h * HD + ch * 4);
    }
#pragma unroll
    for (int t = 0; t < 8; t++) {
        int cid = tid + t * 256;
        int row = cid >> 5, ch = cid & 31;
        size_t src = (size_t)row * (NKV * HD) + (size_t)kvh * HD + ch * 4;
        cp_async16(&Ks[row * AST + ch * 4], g_k + src);
        cp_async16(&Vs[row * AST + ch * 4], g_v + src);
    }
    asm volatile("cp.async.commit_group;\n");

    float mi[4] = {-1e30f, -1e30f, -1e30f, -1e30f};
    float li[4] = {0.f, 0.f, 0.f, 0.f};
    float4 acc0[4] = {{0,0,0,0},{0,0,0,0},{0,0,0,0},{0,0,0,0}};
    float4 acc1[4] = {{0,0,0,0},{0,0,0,0},{0,0,0,0},{0,0,0,0}};

    for (int kt = 0; kt <= qb; kt++) {
        const int cur = kt & 1;
        if (kt < qb) {
            const int nb = cur ^ 1;
#pragma unroll
            for (int t = 0; t < 8; t++) {
                int cid = tid + t * 256;
                int row = cid >> 5, ch = cid & 31;
                size_t src = (size_t)((kt + 1) * 64 + row) * (NKV * HD) +
                             (size_t)kvh * HD + ch * 4;
                cp_async16(&Ks[nb * 64 * AST + row * AST + ch * 4], g_k + src);
                cp_async16(&Vs[nb * 64 * AST + row * AST + ch * 4], g_v + src);
            }
            asm volatile("cp.async.commit_group;\n");
            asm volatile("cp.async.wait_group 1;\n");
        } else {
            asm volatile("cp.async.wait_group 0;\n");
        }
        __syncthreads();

        const float* Kb = Ks + cur * 64 * AST;
        const float* Vb = Vs + cur * 64 * AST;

        // ---- GEMM1: S[4q][4k] over d=128 ----
        float S[4][4] = {};
#pragma unroll 4
        for (int d = 0; d < 128; d += 4) {
            float4 qf[4], kf[4];
#pragma unroll
            for (int i = 0; i < 4; i++)
                qf[i] = *(const float4*)&Qs[(tm * 4 + i) * AST + d];
#pragma unroll
            for (int j = 0; j < 4; j++)
                kf[j] = *(const float4*)&Kb[(tn + 16 * j) * AST + d];
#pragma unroll
            for (int i = 0; i < 4; i++)
#pragma unroll
                for (int j = 0; j < 4; j++) {
                    S[i][j] += qf[i].x * kf[j].x;
                    S[i][j] += qf[i].y * kf[j].y;
                    S[i][j] += qf[i].z * kf[j].z;
                    S[i][j] += qf[i].w * kf[j].w;
                }
        }
#pragma unroll
        for (int i = 0; i < 4; i++)
#pragma unroll
            for (int j = 0; j < 4; j++)
                S[i][j] *= SCALE;

        if (kt == qb) {
#pragma unroll
            for (int i = 0; i < 4; i++)
#pragma unroll
                for (int j = 0; j < 4; j++)
                    if (tn + 16 * j > tm * 4 + i) S[i][j] = -1e30f;
        }

        // ---- tile softmax (online) ----
        float scl[4];
#pragma unroll
        for (int i = 0; i < 4; i++) {
            float t = fmaxf(fmaxf(S[i][0], S[i][1]), fmaxf(S[i][2], S[i][3]));
#pragma unroll
            for (int off = 1; off < 16; off <<= 1)
                t = fmaxf(t, __shfl_xor_sync(0xffffffffu, t, off));
            float nm = fmaxf(mi[i], t);
            scl[i] = __expf(mi[i] - nm);
            mi[i] = nm;
            float p0 = __expf(S[i][0] - nm);
            float p1 = __expf(S[i][1] - nm);
            float p2 = __expf(S[i][2] - nm);
            float p3 = __expf(S[i][3] - nm);
            float rs = (p0 + p1) + (p2 + p3);
#pragma unroll
            for (int off = 1; off < 16; off <<= 1)
                rs += __shfl_xor_sync(0xffffffffu, rs, off);
            li[i] = li[i] * scl[i] + rs;
            float* pr = &Ps[(tm * 4 + i) * PST];
            pr[tn]      = p0;
            pr[tn + 16] = p1;
            pr[tn + 32] = p2;
            pr[tn + 48] = p3;
        }
        __syncthreads();

        // rescale accumulators
#pragma unroll
        for (int i = 0; i < 4; i++) {
            acc0[i].x *= scl[i]; acc0[i].y *= scl[i];
            acc0[i].z *= scl[i]; acc0[i].w *= scl[i];
            acc1[i].x *= scl[i]; acc1[i].y *= scl[i];
            acc1[i].z *= scl[i]; acc1[i].w *= scl[i];
        }

        // ---- GEMM2: acc[4q][8d] += P[4q][64k] x V[64k][8d] ----
#pragma unroll 2
        for (int k = 0; k < 64; k++) {
            float4 v0 = *(const float4*)&Vb[k * AST + tn * 4];
            float4 v1 = *(const float4*)&Vb[k * AST + 64 + tn * 4];
#pragma unroll
            for (int i = 0; i < 4; i++) {
                float p = Ps[(tm * 4 + i) * PST + k];
                acc0[i].x += p * v0.x; acc0[i].y += p * v0.y;
                acc0[i].z += p * v0.z; acc0[i].w += p * v0.w;
                acc1[i].x += p * v1.x; acc1[i].y += p * v1.y;
                acc1[i].z += p * v1.z; acc1[i].w += p * v1.w;
            }
        }
        __syncthreads();
    }

#pragma unroll
    for (int i = 0; i < 4; i++) {
        float inv = __fdiv_rn(1.0f, li[i]);
        float4 o;
        o.x = acc0[i].x * inv; o.y = acc0[i].y * inv;
        o.z = acc0[i].z * inv; o.w = acc0[i].w * inv;
        float* dst = &g_attn[(size_t)(m0 + tm * 4 + i) * (NH * HD) + h * HD];
        *(float4*)&dst[tn * 4] = o;
        o.x = acc1[i].x * inv; o.y = acc1[i].y * inv;
        o.z = acc1[i].z * inv; o.w = acc1[i].w * inv;
        *(float4*)&dst[64 + tn * 4] = o;
    }
}

#define ATTN_SMEM ((64 * AST + 4 * 64 * AST + 64 * PST) * 4)

// ---------------------------------------------------------------------------
// Host launch
// ---------------------------------------------------------------------------
extern "C" void kernel_launch(void* const* d_in, const int* in_sizes, int n_in,
                              void* d_out, int out_size) {
    (void)in_sizes; (void)n_in; (void)out_size;
    const float* hx   = (const float*)d_in[0];
    const float* cosb = (const float*)d_in[1];
    const float* sinb = (const float*)d_in[2];
    const float* Wq   = (const float*)d_in[3];
    const float* Wk   = (const float*)d_in[4];
    const float* Wv   = (const float*)d_in[5];
    const float* Wo   = (const float*)d_in[6];
    float* out = (float*)d_out;

    void *p_xq, *p_sx, *p_wq, *p_swq, *p_wk, *p_swk, *p_wv, *p_swv, *p_wo, *p_swo;
    void *p_q, *p_k, *p_v, *p_attn, *p_aq, *p_sa;
    cudaGetSymbolAddress(&p_xq, g_xq);   cudaGetSymbolAddress(&p_sx, g_sx);
    cudaGetSymbolAddress(&p_wq, g_wq);   cudaGetSymbolAddress(&p_swq, g_swq);
    cudaGetSymbolAddress(&p_wk, g_wk);   cudaGetSymbolAddress(&p_swk, g_swk);
    cudaGetSymbolAddress(&p_wv, g_wv);   cudaGetSymbolAddress(&p_swv, g_swv);
    cudaGetSymbolAddress(&p_wo, g_wo);   cudaGetSymbolAddress(&p_swo, g_swo);
    cudaGetSymbolAddress(&p_q, g_q);     cudaGetSymbolAddress(&p_k, g_k);
    cudaGetSymbolAddress(&p_v, g_v);     cudaGetSymbolAddress(&p_attn, g_attn);
    cudaGetSymbolAddress(&p_aq, g_aq);   cudaGetSymbolAddress(&p_sa, g_sa);

    // allow 72KB dynamic smem for the GEMM
    cudaFuncSetAttribute(gemm_i8mma_kernel,
                         cudaFuncAttributeMaxDynamicSharedMemorySize, GEMM_SMEM);

    // 1. fake-quant activations and weights
    quant_rows_kernel<<<SEQ, 256>>>(hx, (int*)p_xq, (float*)p_sx);
    quant_rows_kernel<<<NH * HD, 256>>>(Wq, (int*)p_wq, (float*)p_swq);
    quant_rows_kernel<<<NKV * HD, 256>>>(Wk, (int*)p_wk, (float*)p_swk);
    quant_rows_kernel<<<NKV * HD, 256>>>(Wv, (int*)p_wv, (float*)p_swv);
    quant_rows_kernel<<<HDIM, 256>>>(Wo, (int*)p_wo, (float*)p_swo);

    // 2. Q projection (grid 512 blocks)
    gemm_i8mma_kernel<<<dim3((NH * HD) / 128, SEQ / 128, 1), 256, GEMM_SMEM>>>(
        (const int*)p_xq, (const float*)p_sx,
        (const int*)p_wq, (const float*)p_swq, (float*)p_q,
        (const int*)p_wq, (const float*)p_swq, (float*)p_q, NH * HD);
    //    K+V projections fused via blockIdx.z (grid 256 blocks, full chip)
    gemm_i8mma_kernel<<<dim3((NKV * HD) / 128, SEQ / 128, 2), 256, GEMM_SMEM>>>(
        (const int*)p_xq, (const float*)p_sx,
        (const int*)p_wk, (const float*)p_swk, (float*)p_k,
        (const int*)p_wv, (const float*)p_swv, (float*)p_v, NKV * HD);

    // 3. RoPE
    rope_kernel<<<(SEQ * NH * 64 + 255) / 256, 256>>>((float*)p_q, cosb, sinb, NH);
    rope_kernel<<<(SEQ * NKV * 64 + 255) / 256, 256>>>((float*)p_k, cosb, sinb, NKV);

    // 4. causal GQA flash attention v2 (heavy-first 1D grid)
    cudaFuncSetAttribute(attn2_kernel, cudaFuncAttributeMaxDynamicSharedMemorySize,
                         ATTN_SMEM);
    attn2_kernel<<<SEQ / 64 * NH, 256, ATTN_SMEM>>>();

    // 5. fake-quant attention output, then O projection into d_out
    quant_rows_kernel<<<SEQ, 256>>>((const float*)p_attn, (int*)p_aq, (float*)p_sa);
    gemm_i8mma_kernel<<<dim3(HDIM / 128, SEQ / 128, 1), 256, GEMM_SMEM>>>(
        (const int*)p_aq, (const float*)p_sa,
        (const int*)p_wo, (const float*)p_swo, out,
        (const int*)p_wo, (const float*)p_swo, out, HDIM);
}

// round 6
// speedup vs baseline: 4.5500x; 1.1611x over previous
#include <cuda_runtime.h>
#include <math_constants.h>
#include <cstdint>

#define SEQ   2048
#define HDIM  4096
#define NH    32
#define NKV   8
#define HD    128
#define KINT  1024          // HDIM / 4 bytes packed per int
#define SCALE 0.08838834764831845f   // 1/sqrt(128)

// ---------------------------------------------------------------------------
// Scratch (static device globals; no runtime allocation)
// ---------------------------------------------------------------------------
__device__ int   g_xq[SEQ * KINT];          // quantized hidden (int8 packed)
__device__ float g_sx[SEQ];
__device__ int   g_wq[(NH * HD) * KINT];
__device__ float g_swq[NH * HD];
__device__ int   g_wk[(NKV * HD) * KINT];
__device__ float g_swk[NKV * HD];
__device__ int   g_wv[(NKV * HD) * KINT];
__device__ float g_swv[NKV * HD];
__device__ int   g_wo[HDIM * KINT];
__device__ float g_swo[HDIM];
__device__ float g_q[SEQ * NH * HD];
__device__ float g_k[SEQ * NKV * HD];
__device__ float g_v[SEQ * NKV * HD];
__device__ float g_attn[SEQ * NH * HD];
__device__ int   g_aq[SEQ * KINT];
__device__ float g_sa[SEQ];

// ---------------------------------------------------------------------------
// Per-row fake-quant: amax/127 scale, round-half-even, pack 4x int8 into int.
// ---------------------------------------------------------------------------
__global__ void quant_rows_kernel(const float* __restrict__ in,
                                  int* __restrict__ outp,
                                  float* __restrict__ scales) {
    const int row = blockIdx.x;
    const int t = threadIdx.x;
    const float4* inr = (const float4*)(in + (size_t)row * HDIM);

    float4 v[4];
    float amax = 0.f;
#pragma unroll
    for (int l = 0; l < 4; l++) {
        v[l] = inr[t + 256 * l];
        amax = fmaxf(amax, fmaxf(fmaxf(fabsf(v[l].x), fabsf(v[l].y)),
                                 fmaxf(fabsf(v[l].z), fabsf(v[l].w))));
    }
    __shared__ float red[256];
    red[t] = amax;
    __syncthreads();
#pragma unroll
    for (int st = 128; st > 0; st >>= 1) {
        if (t < st) red[t] = fmaxf(red[t], red[t + st]);
        __syncthreads();
    }
    float s = __fdiv_rn(red[0], 127.0f);
    s = fmaxf(s, 1e-8f);
    if (t == 0) scales[row] = s;

#pragma unroll
    for (int l = 0; l < 4; l++) {
        float4 x = v[l];
        int a = (int)fminf(fmaxf(rintf(__fdiv_rn(x.x, s)), -128.f), 127.f);
        int b = (int)fminf(fmaxf(rintf(__fdiv_rn(x.y, s)), -128.f), 127.f);
        int c = (int)fminf(fmaxf(rintf(__fdiv_rn(x.z, s)), -128.f), 127.f);
        int d = (int)fminf(fmaxf(rintf(__fdiv_rn(x.w, s)), -128.f), 127.f);
        int p = (a & 0xFF) | ((b & 0xFF) << 8) | ((c & 0xFF) << 16) | (d << 24);
        outp[(size_t)row * KINT + t + 256 * l] = p;
    }
}

// ---------------------------------------------------------------------------
// Int8 tensor-core GEMM (exact): 128x128 tiles, BK=128 bytes (32 ints),
// cp.async double buffer in DYNAMIC shared memory (72KB), 32 iterations.
// ---------------------------------------------------------------------------
#define SMS2 36
#define GEMM_BUFSTRIDE (128 * SMS2)
#define GEMM_SMEM (2 * 2 * GEMM_BUFSTRIDE * 4)   // 73728 bytes

__device__ __forceinline__ void cp_async16(void* smem, const void* g) {
    uint32_t s = (uint32_t)__cvta_generic_to_shared(smem);
    asm volatile("cp.async.cg.shared.global [%0], [%1], 16;\n" :: "r"(s), "l"(g));
}

__device__ __forceinline__ void mma_i8(int& c0, int& c1, int& c2, int& c3,
                                       int a0, int a1, int a2, int a3,
                                       int b0, int b1) {
    asm volatile(
        "mma.sync.aligned.m16n8k32.row.col.s32.s8.s8.s32 "
        "{%0,%1,%2,%3}, {%4,%5,%6,%7}, {%8,%9}, {%0,%1,%2,%3};\n"
        : "+r"(c0), "+r"(c1), "+r"(c2), "+r"(c3)
        : "r"(a0), "r"(a1), "r"(a2), "r"(a3), "r"(b0), "r"(b1));
}

__global__ __launch_bounds__(256, 2)
void gemm_i8mma_kernel(const int* __restrict__ A, const float* __restrict__ sa,
                       const int* __restrict__ B0, const float* __restrict__ sb0,
                       float* __restrict__ Y0,
                       const int* __restrict__ B1, const float* __restrict__ sb1,
                       float* __restrict__ Y1, int N) {
    const int* __restrict__ B = blockIdx.z ? B1 : B0;
    const float* __restrict__ sb = blockIdx.z ? sb1 : sb0;
    float* __restrict__ Y = blockIdx.z ? Y1 : Y0;

    extern __shared__ int dynsmem[];
    int* As = dynsmem;
    int* Bs = dynsmem + 2 * GEMM_BUFSTRIDE;

    const int tid = threadIdx.x;
    const int warp = tid >> 5;
    const int lane = tid & 31;
    const int wm = warp >> 2;
    const int wn = warp & 3;
    const int lr = lane >> 2;
    const int c  = lane & 3;
    const int m0 = blockIdx.y * 128;
    const int n0 = blockIdx.x * 128;

    const int r0 = tid >> 3;
    const int ch = tid & 7;

    const int* Ag[4];
    const int* Bg[4];
    int* Asw[4];
    int* Bsw[4];
#pragma unroll
    for (int rr = 0; rr < 4; rr++) {
        int row = r0 + 32 * rr;
        Ag[rr] = A + (size_t)(m0 + row) * KINT + ch * 4;
        Bg[rr] = B + (size_t)(n0 + row) * KINT + ch * 4;
        Asw[rr] = &As[row * SMS2 + ch * 4];
        Bsw[rr] = &Bs[row * SMS2 + ch * 4];
    }

    int acc[4][4][4] = {};

#pragma unroll
    for (int rr = 0; rr < 4; rr++) {
        cp_async16(Asw[rr], Ag[rr]);
        cp_async16(Bsw[rr], Bg[rr]);
    }
    asm volatile("cp.async.commit_group;\n");

    const int* Afrag = &As[(wm * 64 + lr) * SMS2 + c];
    const int* Bfrag = &Bs[(wn * 32 + lr) * SMS2 + c];

    for (int it = 0; it < 32; it++) {
        int cur = it & 1;
        if (it < 31) {
            int nb = (it + 1) & 1;
            int ko = (it + 1) * 32;
#pragma unroll
            for (int rr = 0; rr < 4; rr++) {
                cp_async16(Asw[rr] + nb * GEMM_BUFSTRIDE, Ag[rr] + ko);
                cp_async16(Bsw[rr] + nb * GEMM_BUFSTRIDE, Bg[rr] + ko);
            }
            asm volatile("cp.async.commit_group;\n");
            asm volatile("cp.async.wait_group 1;\n");
        } else {
            asm volatile("cp.async.wait_group 0;\n");
        }
        __syncthreads();

        const int* Af = Afrag + cur * GEMM_BUFSTRIDE;
        const int* Bf = Bfrag + cur * GEMM_BUFSTRIDE;
#pragma unroll
        for (int ks = 0; ks < 4; ks++) {
            int a[4][4], b[4][2];
#pragma unroll
            for (int i = 0; i < 4; i++) {
                a[i][0] = Af[i * 16 * SMS2 + ks * 8];
                a[i][1] = Af[i * 16 * SMS2 + 8 * SMS2 + ks * 8];
                a[i][2] = Af[i * 16 * SMS2 + ks * 8 + 4];
                a[i][3] = Af[i * 16 * SMS2 + 8 * SMS2 + ks * 8 + 4];
            }
#pragma unroll
            for (int j = 0; j < 4; j++) {
                b[j][0] = Bf[j * 8 * SMS2 + ks * 8];
                b[j][1] = Bf[j * 8 * SMS2 + ks * 8 + 4];
            }
#pragma unroll
            for (int i = 0; i < 4; i++)
#pragma unroll
                for (int j = 0; j < 4; j++)
                    mma_i8(acc[i][j][0], acc[i][j][1], acc[i][j][2], acc[i][j][3],
                           a[i][0], a[i][1], a[i][2], a[i][3], b[j][0], b[j][1]);
        }
        __syncthreads();
    }

    float sav0[4], sav8[4];
#pragma unroll
    for (int i = 0; i < 4; i++) {
        sav0[i] = sa[m0 + wm * 64 + i * 16 + lr];
        sav8[i] = sa[m0 + wm * 64 + i * 16 + lr + 8];
    }
    float2 sbv[4];
#pragma unroll
    for (int j = 0; j < 4; j++) {
        int n = n0 + wn * 32 + j * 8 + 2 * c;
        sbv[j].x = sb[n];
        sbv[j].y = sb[n + 1];
    }
#pragma unroll
    for (int i = 0; i < 4; i++) {
        int mrow0 = m0 + wm * 64 + i * 16 + lr;
#pragma unroll
        for (int j = 0; j < 4; j++) {
            int n = n0 + wn * 32 + j * 8 + 2 * c;
            float2 o;
            o.x = (float)acc[i][j][0] * sav0[i] * sbv[j].x;
            o.y = (float)acc[i][j][1] * sav0[i] * sbv[j].y;
            *(float2*)&Y[(size_t)mrow0 * N + n] = o;
            o.x = (float)acc[i][j][2] * sav8[i] * sbv[j].x;
            o.y = (float)acc[i][j][3] * sav8[i] * sbv[j].y;
            *(float2*)&Y[(size_t)(mrow0 + 8) * N + n] = o;
        }
    }
}

// ---------------------------------------------------------------------------
// RoPE in-place on [S][nh*128]: pairs (d, d+64) per head
// ---------------------------------------------------------------------------
__global__ void rope_kernel(float* __restrict__ x, const float* __restrict__ cosb,
                            const float* __restrict__ sinb, int nh) {
    int idx = blockIdx.x * blockDim.x + threadIdx.x;
    int total = SEQ * nh * 64;
    if (idx >= total) return;
    int d = idx & 63;
    int h = (idx >> 6) % nh;
    int t = idx / (nh * 64);
    float c = cosb[t * 128 + d];
    float s = sinb[t * 128 + d];
    float* p = x + (size_t)t * nh * 128 + h * 128 + d;
    float x1 = p[0], x2 = p[64];
    p[0]  = x1 * c - x2 * s;
    p[64] = x2 * c + x1 * s;
}

// ---------------------------------------------------------------------------
// f32x2 packed-FMA helpers (Blackwell FFMA2: 2 IEEE fp32 FMAs per instr)
// ---------------------------------------------------------------------------
__device__ __forceinline__ void ffma2(unsigned long long& d,
                                      unsigned long long a,
                                      unsigned long long b) {
    asm("fma.rn.f32x2 %0, %1, %2, %0;" : "+l"(d) : "l"(a), "l"(b));
}
__device__ __forceinline__ unsigned long long pack2(float x) {
    unsigned long long r;
    asm("mov.b64 %0, {%1, %1};" : "=l"(r) : "f"(x));
    return r;
}
__device__ __forceinline__ void mul2(unsigned long long& d, unsigned long long s) {
    asm("mul.rn.f32x2 %0, %0, %1;" : "+l"(d) : "l"(s));
}
__device__ __forceinline__ float2 unpack2(unsigned long long a) {
    float2 f;
    asm("mov.b64 {%0, %1}, %2;" : "=f"(f.x), "=f"(f.y) : "l"(a));
    return f;
}

// ---------------------------------------------------------------------------
// Causal GQA flash attention v3: f32x2-packed register GEMMs.
// Block: 128 q-rows x head; KV tiles of 64 keys. 256 threads.
// Thread (tm,tn): tm=tid>>4 owns q rows tm*8..+7; S cols tn+16j (j<4);
// PV/O d-cols 4tn..+3 and 64+4tn..+3. P transposed through smem.
// K double-buffered cp.async; V single-buffer software pipeline; Q resident.
// Accumulation pairs split even/odd d (exact fp32 math, reordered).
// ---------------------------------------------------------------------------
#define QST 128
#define KST 132
#define PTST 132
#define ATTN3_SMEM ((128 * QST + 3 * 64 * KST + 64 * PTST) * 4)  // 200704 B

__global__ __launch_bounds__(256) void attn3_kernel() {
    extern __shared__ float sh[];
    float* Qs = sh;                         // 128 x QST
    float* Ks = Qs + 128 * QST;             // 2 x 64 x KST
    float* Vs = Ks + 2 * 64 * KST;          // 64 x KST
    float* Pt = Vs + 64 * KST;              // 64 x PTST (P transposed: [k][q])

    const int bid = blockIdx.x;
    const int qb  = 15 - (bid >> 5);        // heavy-first
    const int h   = bid & 31;
    const int kvh = h >> 2;
    const int tid = threadIdx.x;
    const int tm  = tid >> 4;               // 0..15
    const int tn  = tid & 15;               // 0..15
    const int m0  = qb * 128;
    const int ktmax = 2 * qb + 2;

    // ---- stage Q (128x128) + K tile 0 as group 0 ----
#pragma unroll
    for (int t = 0; t < 16; t++) {
        int cid = tid + t * 256;
        int row = cid >> 5, ch = cid & 31;
        cp_async16(&Qs[row * QST + ch * 4],
                   g_q + (size_t)(m0 + row) * (NH * HD) + h * HD + ch * 4);
    }
#pragma unroll
    for (int t = 0; t < 8; t++) {
        int cid = tid + t * 256;
        int row = cid >> 5, ch = cid & 31;
        cp_async16(&Ks[row * KST + ch * 4],
                   g_k + (size_t)row * (NKV * HD) + (size_t)kvh * HD + ch * 4);
    }
    asm volatile("cp.async.commit_group;\n");
    // ---- V tile 0 as group 1 ----
#pragma unroll
    for (int t = 0; t < 8; t++) {
        int cid = tid + t * 256;
        int row = cid >> 5, ch = cid & 31;
        cp_async16(&Vs[row * KST + ch * 4],
                   g_v + (size_t)row * (NKV * HD) + (size_t)kvh * HD + ch * 4);
    }
    asm volatile("cp.async.commit_group;\n");

    float mi[8], li[8];
#pragma unroll
    for (int i = 0; i < 8; i++) { mi[i] = -1e30f; li[i] = 0.f; }
    unsigned long long accv[8][4] = {};     // PV acc: [row][0,1]=d 4tn; [2,3]=64+4tn

    for (int kt = 0; kt < ktmax; kt++) {
        const int cur = kt & 1;
        const bool last = (kt == ktmax - 1);

        // K(kt) ready (V(kt) may still be in flight)
        asm volatile("cp.async.wait_group 1;\n");
        __syncthreads();

        // prefetch K(kt+1) into alt buffer (doesn't touch cur)
        if (!last) {
#pragma unroll
            for (int t = 0; t < 8; t++) {
                int cid = tid + t * 256;
                int row = cid >> 5, ch = cid & 31;
                cp_async16(&Ks[(cur ^ 1) * 64 * KST + row * KST + ch * 4],
                           g_k + (size_t)((kt + 1) * 64 + row) * (NKV * HD) +
                               (size_t)kvh * HD + ch * 4);
            }
            asm volatile("cp.async.commit_group;\n");
        }

        // ---- GEMM1: S[8 rows][4 cols] over d=128, packed pairs ----
        const float* Kb = Ks + cur * 64 * KST;
        unsigned long long S2[8][4] = {};
#pragma unroll 4
        for (int d = 0; d < 128; d += 4) {
            ulonglong2 qp[8], kp[4];
#pragma unroll
            for (int i = 0; i < 8; i++)
                qp[i] = *(const ulonglong2*)&Qs[(tm * 8 + i) * QST + d];
#pragma unroll
            for (int j = 0; j < 4; j++)
                kp[j] = *(const ulonglong2*)&Kb[(tn + 16 * j) * KST + d];
#pragma unroll
            for (int i = 0; i < 8; i++)
#pragma unroll
                for (int j = 0; j < 4; j++) {
                    ffma2(S2[i][j], qp[i].x, kp[j].x);
                    ffma2(S2[i][j], qp[i].y, kp[j].y);
                }
        }

        // ---- tile softmax (online), write P transposed ----
        const bool diag = (kt >= 2 * qb);
        float scl[8];
#pragma unroll
        for (int i = 0; i < 8; i++) {
            float s[4];
#pragma unroll
            for (int j = 0; j < 4; j++) {
                float2 u = unpack2(S2[i][j]);
                s[j] = (u.x + u.y) * SCALE;
            }
            if (diag) {
                int rowg = m0 + tm * 8 + i;
#pragma unroll
                for (int j = 0; j < 4; j++)
                    if (kt * 64 + tn + 16 * j > rowg) s[j] = -1e30f;
            }
            float t = fmaxf(fmaxf(s[0], s[1]), fmaxf(s[2], s[3]));
#pragma unroll
            for (int off = 1; off < 16; off <<= 1)
                t = fmaxf(t, __shfl_xor_sync(0xffffffffu, t, off));
            float nm = fmaxf(mi[i], t);
            scl[i] = __expf(mi[i] - nm);
            mi[i] = nm;
            float p0 = __expf(s[0] - nm);
            float p1 = __expf(s[1] - nm);
            float p2 = __expf(s[2] - nm);
            float p3 = __expf(s[3] - nm);
            float rs = (p0 + p1) + (p2 + p3);
#pragma unroll
            for (int off = 1; off < 16; off <<= 1)
                rs += __shfl_xor_sync(0xffffffffu, rs, off);
            li[i] = li[i] * scl[i] + rs;
            Pt[(tn     ) * PTST + tm * 8 + i] = p0;
            Pt[(tn + 16) * PTST + tm * 8 + i] = p1;
            Pt[(tn + 32) * PTST + tm * 8 + i] = p2;
            Pt[(tn + 48) * PTST + tm * 8 + i] = p3;
        }

        // V(kt) ready + Pt visible after one barrier
        if (last) asm volatile("cp.async.wait_group 0;\n");
        else      asm volatile("cp.async.wait_group 1;\n");
        __syncthreads();

        // rescale PV accumulators (packed)
#pragma unroll
        for (int i = 0; i < 8; i++) {
            unsigned long long s2 = pack2(scl[i]);
            mul2(accv[i][0], s2);
            mul2(accv[i][1], s2);
            mul2(accv[i][2], s2);
            mul2(accv[i][3], s2);
        }

        // ---- GEMM2: acc[8 rows][8 d] += P^T x V over 64 keys, packed ----
#pragma unroll 4
        for (int k = 0; k < 64; k++) {
            ulonglong2 v0 = *(const ulonglong2*)&Vs[k * KST + 4 * tn];
            ulonglong2 v1 = *(const ulonglong2*)&Vs[k * KST + 64 + 4 * tn];
            float4 pa = *(const float4*)&Pt[k * PTST + tm * 8];
            float4 pb = *(const float4*)&Pt[k * PTST + tm * 8 + 4];
            float pv[8] = {pa.x, pa.y, pa.z, pa.w, pb.x, pb.y, pb.z, pb.w};
#pragma unroll
            for (int i = 0; i < 8; i++) {
                unsigned long long pp = pack2(pv[i]);
                ffma2(accv[i][0], pp, v0.x);
                ffma2(accv[i][1], pp, v0.y);
                ffma2(accv[i][2], pp, v1.x);
                ffma2(accv[i][3], pp, v1.y);
            }
        }
        __syncthreads();   // Vs and Pt free for next tile

        // pipeline V(kt+1) into the single V buffer
        if (!last) {
#pragma unroll
            for (int t = 0; t < 8; t++) {
                int cid = tid + t * 256;
                int row = cid >> 5, ch = cid & 31;
                cp_async16(&Vs[row * KST + ch * 4],
                           g_v + (size_t)((kt + 1) * 64 + row) * (NKV * HD) +
                               (size_t)kvh * HD + ch * 4);
            }
            asm volatile("cp.async.commit_group;\n");
        }
    }

    // ---- epilogue: normalize and store ----
#pragma unroll
    for (int i = 0; i < 8; i++) {
        float inv = __fdiv_rn(1.0f, li[i]);
        float2 a0 = unpack2(accv[i][0]);
        float2 a1 = unpack2(accv[i][1]);
        float2 a2 = unpack2(accv[i][2]);
        float2 a3 = unpack2(accv[i][3]);
        float* dst = &g_attn[(size_t)(m0 + tm * 8 + i) * (NH * HD) + h * HD];
        float4 o;
        o.x = a0.x * inv; o.y = a0.y * inv; o.z = a1.x * inv; o.w = a1.y * inv;
        *(float4*)&dst[4 * tn] = o;
        o.x = a2.x * inv; o.y = a2.y * inv; o.z = a3.x * inv; o.w = a3.y * inv;
        *(float4*)&dst[64 + 4 * tn] = o;
    }
}

// ---------------------------------------------------------------------------
// Host launch
// ---------------------------------------------------------------------------
extern "C" void kernel_launch(void* const* d_in, const int* in_sizes, int n_in,
                              void* d_out, int out_size) {
    (void)in_sizes; (void)n_in; (void)out_size;
    const float* hx   = (const float*)d_in[0];
    const float* cosb = (const float*)d_in[1];
    const float* sinb = (const float*)d_in[2];
    const float* Wq   = (const float*)d_in[3];
    const float* Wk   = (const float*)d_in[4];
    const float* Wv   = (const float*)d_in[5];
    const float* Wo   = (const float*)d_in[6];
    float* out = (float*)d_out;

    void *p_xq, *p_sx, *p_wq, *p_swq, *p_wk, *p_swk, *p_wv, *p_swv, *p_wo, *p_swo;
    void *p_q, *p_k, *p_v, *p_attn, *p_aq, *p_sa;
    cudaGetSymbolAddress(&p_xq, g_xq);   cudaGetSymbolAddress(&p_sx, g_sx);
    cudaGetSymbolAddress(&p_wq, g_wq);   cudaGetSymbolAddress(&p_swq, g_swq);
    cudaGetSymbolAddress(&p_wk, g_wk);   cudaGetSymbolAddress(&p_swk, g_swk);
    cudaGetSymbolAddress(&p_wv, g_wv);   cudaGetSymbolAddress(&p_swv, g_swv);
    cudaGetSymbolAddress(&p_wo, g_wo);   cudaGetSymbolAddress(&p_swo, g_swo);
    cudaGetSymbolAddress(&p_q, g_q);     cudaGetSymbolAddress(&p_k, g_k);
    cudaGetSymbolAddress(&p_v, g_v);     cudaGetSymbolAddress(&p_attn, g_attn);
    cudaGetSymbolAddress(&p_aq, g_aq);   cudaGetSymbolAddress(&p_sa, g_sa);

    cudaFuncSetAttribute(gemm_i8mma_kernel,
                         cudaFuncAttributeMaxDynamicSharedMemorySize, GEMM_SMEM);
    cudaFuncSetAttribute(attn3_kernel,
                         cudaFuncAttributeMaxDynamicSharedMemorySize, ATTN3_SMEM);

    // 1. fake-quant activations and weights
    quant_rows_kernel<<<SEQ, 256>>>(hx, (int*)p_xq, (float*)p_sx);
    quant_rows_kernel<<<NH * HD, 256>>>(Wq, (int*)p_wq, (float*)p_swq);
    quant_rows_kernel<<<NKV * HD, 256>>>(Wk, (int*)p_wk, (float*)p_swk);
    quant_rows_kernel<<<NKV * HD, 256>>>(Wv, (int*)p_wv, (float*)p_swv);
    quant_rows_kernel<<<HDIM, 256>>>(Wo, (int*)p_wo, (float*)p_swo);

    // 2. Q projection; K+V fused via blockIdx.z
    gemm_i8mma_kernel<<<dim3((NH * HD) / 128, SEQ / 128, 1), 256, GEMM_SMEM>>>(
        (const int*)p_xq, (const float*)p_sx,
        (const int*)p_wq, (const float*)p_swq, (float*)p_q,
        (const int*)p_wq, (const float*)p_swq, (float*)p_q, NH * HD);
    gemm_i8mma_kernel<<<dim3((NKV * HD) / 128, SEQ / 128, 2), 256, GEMM_SMEM>>>(
        (const int*)p_xq, (const float*)p_sx,
        (const int*)p_wk, (const float*)p_swk, (float*)p_k,
        (const int*)p_wv, (const float*)p_swv, (float*)p_v, NKV * HD);

    // 3. RoPE
    rope_kernel<<<(SEQ * NH * 64 + 255) / 256, 256>>>((float*)p_q, cosb, sinb, NH);
    rope_kernel<<<(SEQ * NKV * 64 + 255) / 256, 256>>>((float*)p_k, cosb, sinb, NKV);

    // 4. causal GQA flash attention v3 (f32x2-packed, heavy-first)
    attn3_kernel<<<(SEQ / 128) * NH, 256, ATTN3_SMEM>>>();

    // 5. fake-quant attention output, then O projection into d_out
    quant_rows_kernel<<<SEQ, 256>>>((const float*)p_attn, (int*)p_aq, (float*)p_sa);
    gemm_i8mma_kernel<<<dim3(HDIM / 128, SEQ / 128, 1), 256, GEMM_SMEM>>>(
        (const int*)p_aq, (const float*)p_sa,
        (const int*)p_wo, (const float*)p_swo, out,
        (const int*)p_wo, (const float*)p_swo, out, HDIM);
}

// round 7
// speedup vs baseline: 4.6564x; 1.0234x over previous
#include <cuda_runtime.h>
#include <math_constants.h>
#include <cstdint>

#define SEQ   2048
#define HDIM  4096
#define NH    32
#define NKV   8
#define HD    128
#define KINT  1024          // HDIM / 4 bytes packed per int
#define SCALE 0.08838834764831845f   // 1/sqrt(128)

// ---------------------------------------------------------------------------
// Scratch (static device globals; no runtime allocation)
// ---------------------------------------------------------------------------
__device__ int   g_xq[SEQ * KINT];          // quantized hidden (int8 packed)
__device__ float g_sx[SEQ];
__device__ int   g_wq[(NH * HD) * KINT];
__device__ float g_swq[NH * HD];
__device__ int   g_wk[(NKV * HD) * KINT];
__device__ float g_swk[NKV * HD];
__device__ int   g_wv[(NKV * HD) * KINT];
__device__ float g_swv[NKV * HD];
__device__ int   g_wo[HDIM * KINT];
__device__ float g_swo[HDIM];
__device__ float g_q[SEQ * NH * HD];
__device__ float g_k[SEQ * NKV * HD];
__device__ float g_v[SEQ * NKV * HD];
__device__ float g_attn[SEQ * NH * HD];
__device__ int   g_aq[SEQ * KINT];
__device__ float g_sa[SEQ];

// ---------------------------------------------------------------------------
// Per-row fake-quant: amax/127 scale, round-half-even, pack 4x int8 into int.
// ---------------------------------------------------------------------------
__global__ void quant_rows_kernel(const float* __restrict__ in,
                                  int* __restrict__ outp,
                                  float* __restrict__ scales) {
    const int row = blockIdx.x;
    const int t = threadIdx.x;
    const float4* inr = (const float4*)(in + (size_t)row * HDIM);

    float4 v[4];
    float amax = 0.f;
#pragma unroll
    for (int l = 0; l < 4; l++) {
        v[l] = inr[t + 256 * l];
        amax = fmaxf(amax, fmaxf(fmaxf(fabsf(v[l].x), fabsf(v[l].y)),
                                 fmaxf(fabsf(v[l].z), fabsf(v[l].w))));
    }
    __shared__ float red[256];
    red[t] = amax;
    __syncthreads();
#pragma unroll
    for (int st = 128; st > 0; st >>= 1) {
        if (t < st) red[t] = fmaxf(red[t], red[t + st]);
        __syncthreads();
    }
    float s = __fdiv_rn(red[0], 127.0f);
    s = fmaxf(s, 1e-8f);
    if (t == 0) scales[row] = s;

#pragma unroll
    for (int l = 0; l < 4; l++) {
        float4 x = v[l];
        int a = (int)fminf(fmaxf(rintf(__fdiv_rn(x.x, s)), -128.f), 127.f);
        int b = (int)fminf(fmaxf(rintf(__fdiv_rn(x.y, s)), -128.f), 127.f);
        int c = (int)fminf(fmaxf(rintf(__fdiv_rn(x.z, s)), -128.f), 127.f);
        int d = (int)fminf(fmaxf(rintf(__fdiv_rn(x.w, s)), -128.f), 127.f);
        int p = (a & 0xFF) | ((b & 0xFF) << 8) | ((c & 0xFF) << 16) | (d << 24);
        outp[(size_t)row * KINT + t + 256 * l] = p;
    }
}

// ---------------------------------------------------------------------------
// Int8 tensor-core GEMM (exact): 128x128 tiles, BK=128 bytes (32 ints),
// cp.async double buffer in DYNAMIC shared memory (72KB), 32 iterations.
// ---------------------------------------------------------------------------
#define SMS2 36
#define GEMM_BUFSTRIDE (128 * SMS2)
#define GEMM_SMEM (2 * 2 * GEMM_BUFSTRIDE * 4)   // 73728 bytes

__device__ __forceinline__ void cp_async16(void* smem, const void* g) {
    uint32_t s = (uint32_t)__cvta_generic_to_shared(smem);
    asm volatile("cp.async.cg.shared.global [%0], [%1], 16;\n" :: "r"(s), "l"(g));
}

__device__ __forceinline__ void mma_i8(int& c0, int& c1, int& c2, int& c3,
                                       int a0, int a1, int a2, int a3,
                                       int b0, int b1) {
    asm volatile(
        "mma.sync.aligned.m16n8k32.row.col.s32.s8.s8.s32 "
        "{%0,%1,%2,%3}, {%4,%5,%6,%7}, {%8,%9}, {%0,%1,%2,%3};\n"
        : "+r"(c0), "+r"(c1), "+r"(c2), "+r"(c3)
        : "r"(a0), "r"(a1), "r"(a2), "r"(a3), "r"(b0), "r"(b1));
}

__global__ __launch_bounds__(256, 2)
void gemm_i8mma_kernel(const int* __restrict__ A, const float* __restrict__ sa,
                       const int* __restrict__ B0, const float* __restrict__ sb0,
                       float* __restrict__ Y0,
                       const int* __restrict__ B1, const float* __restrict__ sb1,
                       float* __restrict__ Y1, int N) {
    const int* __restrict__ B = blockIdx.z ? B1 : B0;
    const float* __restrict__ sb = blockIdx.z ? sb1 : sb0;
    float* __restrict__ Y = blockIdx.z ? Y1 : Y0;

    extern __shared__ int dynsmem[];
    int* As = dynsmem;
    int* Bs = dynsmem + 2 * GEMM_BUFSTRIDE;

    const int tid = threadIdx.x;
    const int warp = tid >> 5;
    const int lane = tid & 31;
    const int wm = warp >> 2;
    const int wn = warp & 3;
    const int lr = lane >> 2;
    const int c  = lane & 3;
    const int m0 = blockIdx.y * 128;
    const int n0 = blockIdx.x * 128;

    const int r0 = tid >> 3;
    const int ch = tid & 7;

    const int* Ag[4];
    const int* Bg[4];
    int* Asw[4];
    int* Bsw[4];
#pragma unroll
    for (int rr = 0; rr < 4; rr++) {
        int row = r0 + 32 * rr;
        Ag[rr] = A + (size_t)(m0 + row) * KINT + ch * 4;
        Bg[rr] = B + (size_t)(n0 + row) * KINT + ch * 4;
        Asw[rr] = &As[row * SMS2 + ch * 4];
        Bsw[rr] = &Bs[row * SMS2 + ch * 4];
    }

    int acc[4][4][4] = {};

#pragma unroll
    for (int rr = 0; rr < 4; rr++) {
        cp_async16(Asw[rr], Ag[rr]);
        cp_async16(Bsw[rr], Bg[rr]);
    }
    asm volatile("cp.async.commit_group;\n");

    const int* Afrag = &As[(wm * 64 + lr) * SMS2 + c];
    const int* Bfrag = &Bs[(wn * 32 + lr) * SMS2 + c];

    for (int it = 0; it < 32; it++) {
        int cur = it & 1;
        if (it < 31) {
            int nb = (it + 1) & 1;
            int ko = (it + 1) * 32;
#pragma unroll
            for (int rr = 0; rr < 4; rr++) {
                cp_async16(Asw[rr] + nb * GEMM_BUFSTRIDE, Ag[rr] + ko);
                cp_async16(Bsw[rr] + nb * GEMM_BUFSTRIDE, Bg[rr] + ko);
            }
            asm volatile("cp.async.commit_group;\n");
            asm volatile("cp.async.wait_group 1;\n");
        } else {
            asm volatile("cp.async.wait_group 0;\n");
        }
        __syncthreads();

        const int* Af = Afrag + cur * GEMM_BUFSTRIDE;
        const int* Bf = Bfrag + cur * GEMM_BUFSTRIDE;
#pragma unroll
        for (int ks = 0; ks < 4; ks++) {
            int a[4][4], b[4][2];
#pragma unroll
            for (int i = 0; i < 4; i++) {
                a[i][0] = Af[i * 16 * SMS2 + ks * 8];
                a[i][1] = Af[i * 16 * SMS2 + 8 * SMS2 + ks * 8];
                a[i][2] = Af[i * 16 * SMS2 + ks * 8 + 4];
                a[i][3] = Af[i * 16 * SMS2 + 8 * SMS2 + ks * 8 + 4];
            }
#pragma unroll
            for (int j = 0; j < 4; j++) {
                b[j][0] = Bf[j * 8 * SMS2 + ks * 8];
                b[j][1] = Bf[j * 8 * SMS2 + ks * 8 + 4];
            }
#pragma unroll
            for (int i = 0; i < 4; i++)
#pragma unroll
                for (int j = 0; j < 4; j++)
                    mma_i8(acc[i][j][0], acc[i][j][1], acc[i][j][2], acc[i][j][3],
                           a[i][0], a[i][1], a[i][2], a[i][3], b[j][0], b[j][1]);
        }
        __syncthreads();
    }

    float sav0[4], sav8[4];
#pragma unroll
    for (int i = 0; i < 4; i++) {
        sav0[i] = sa[m0 + wm * 64 + i * 16 + lr];
        sav8[i] = sa[m0 + wm * 64 + i * 16 + lr + 8];
    }
    float2 sbv[4];
#pragma unroll
    for (int j = 0; j < 4; j++) {
        int n = n0 + wn * 32 + j * 8 + 2 * c;
        sbv[j].x = sb[n];
        sbv[j].y = sb[n + 1];
    }
#pragma unroll
    for (int i = 0; i < 4; i++) {
        int mrow0 = m0 + wm * 64 + i * 16 + lr;
#pragma unroll
        for (int j = 0; j < 4; j++) {
            int n = n0 + wn * 32 + j * 8 + 2 * c;
            float2 o;
            o.x = (float)acc[i][j][0] * sav0[i] * sbv[j].x;
            o.y = (float)acc[i][j][1] * sav0[i] * sbv[j].y;
            *(float2*)&Y[(size_t)mrow0 * N + n] = o;
            o.x = (float)acc[i][j][2] * sav8[i] * sbv[j].x;
            o.y = (float)acc[i][j][3] * sav8[i] * sbv[j].y;
            *(float2*)&Y[(size_t)(mrow0 + 8) * N + n] = o;
        }
    }
}

// ---------------------------------------------------------------------------
// Fused RoPE for Q and K in one launch: virtual heads 0..39 (32 q + 8 k)
// ---------------------------------------------------------------------------
__global__ void rope_all_kernel(float* __restrict__ q, float* __restrict__ k,
                                const float* __restrict__ cosb,
                                const float* __restrict__ sinb) {
    int idx = blockIdx.x * blockDim.x + threadIdx.x;
    const int total = SEQ * (NH + NKV) * 64;
    if (idx >= total) return;
    int d = idx & 63;
    int h = (idx >> 6) % (NH + NKV);
    int t = idx / ((NH + NKV) * 64);
    float c = cosb[t * 128 + d];
    float s = sinb[t * 128 + d];
    float* p = (h < NH)
        ? q + (size_t)t * NH * 128 + h * 128 + d
        : k + (size_t)t * NKV * 128 + (h - NH) * 128 + d;
    float x1 = p[0], x2 = p[64];
    p[0]  = x1 * c - x2 * s;
    p[64] = x2 * c + x1 * s;
}

// ---------------------------------------------------------------------------
// f32x2 packed-FMA helpers (Blackwell FFMA2: 2 IEEE fp32 FMAs per instr)
// ---------------------------------------------------------------------------
__device__ __forceinline__ void ffma2(unsigned long long& d,
                                      unsigned long long a,
                                      unsigned long long b) {
    asm("fma.rn.f32x2 %0, %1, %2, %0;" : "+l"(d) : "l"(a), "l"(b));
}
__device__ __forceinline__ unsigned long long pack2(float x) {
    unsigned long long r;
    asm("mov.b64 %0, {%1, %1};" : "=l"(r) : "f"(x));
    return r;
}
__device__ __forceinline__ void mul2(unsigned long long& d, unsigned long long s) {
    asm("mul.rn.f32x2 %0, %0, %1;" : "+l"(d) : "l"(s));
}
__device__ __forceinline__ float2 unpack2(unsigned long long a) {
    float2 f;
    asm("mov.b64 {%0, %1}, %2;" : "=f"(f.x), "=f"(f.y) : "l"(a));
    return f;
}

// ---------------------------------------------------------------------------
// Causal GQA flash attention v4: f32x2-packed register GEMMs, 512 threads.
// Block: 128 q-rows x head; KV tiles of 64 keys. 16 warps = 4/SMSP for
// latency hiding (v3's 2/SMSP was the issue-efficiency bottleneck).
// Thread (tm=tid>>4 in 0..31, tn=tid&15): 4 q rows, S cols tn+16j;
// PV/O d-cols 4tn..+3 and 64+4tn..+3. P transposed through smem.
// K double-buffered cp.async; V single-buffer software pipeline; Q resident.
// Per-element arithmetic identical to v3 (same pairing/order).
// ---------------------------------------------------------------------------
#define QST 128
#define KST 132
#define PTST 132
#define ATTN3_SMEM ((128 * QST + 3 * 64 * KST + 64 * PTST) * 4)  // 200704 B

__global__ __launch_bounds__(512) void attn4_kernel() {
    extern __shared__ float sh[];
    float* Qs = sh;                         // 128 x QST
    float* Ks = Qs + 128 * QST;             // 2 x 64 x KST
    float* Vs = Ks + 2 * 64 * KST;          // 64 x KST
    float* Pt = Vs + 64 * KST;              // 64 x PTST (P transposed: [k][q])

    const int bid = blockIdx.x;
    const int qb  = 15 - (bid >> 5);        // heavy-first
    const int h   = bid & 31;
    const int kvh = h >> 2;
    const int tid = threadIdx.x;
    const int tm  = tid >> 4;               // 0..31
    const int tn  = tid & 15;               // 0..15
    const int m0  = qb * 128;
    const int ktmax = 2 * qb + 2;

    // ---- stage Q (128x128) + K tile 0 as group 0 ----
#pragma unroll
    for (int t = 0; t < 8; t++) {
        int cid = tid + t * 512;
        int row = cid >> 5, ch = cid & 31;
        cp_async16(&Qs[row * QST + ch * 4],
                   g_q + (size_t)(m0 + row) * (NH * HD) + h * HD + ch * 4);
    }
#pragma unroll
    for (int t = 0; t < 4; t++) {
        int cid = tid + t * 512;
        int row = cid >> 5, ch = cid & 31;
        cp_async16(&Ks[row * KST + ch * 4],
                   g_k + (size_t)row * (NKV * HD) + (size_t)kvh * HD + ch * 4);
    }
    asm volatile("cp.async.commit_group;\n");
    // ---- V tile 0 as group 1 ----
#pragma unroll
    for (int t = 0; t < 4; t++) {
        int cid = tid + t * 512;
        int row = cid >> 5, ch = cid & 31;
        cp_async16(&Vs[row * KST + ch * 4],
                   g_v + (size_t)row * (NKV * HD) + (size_t)kvh * HD + ch * 4);
    }
    asm volatile("cp.async.commit_group;\n");

    float mi[4], li[4];
#pragma unroll
    for (int i = 0; i < 4; i++) { mi[i] = -1e30f; li[i] = 0.f; }
    unsigned long long accv[4][4] = {};     // [row][0,1]=d 4tn; [2,3]=64+4tn

    for (int kt = 0; kt < ktmax; kt++) {
        const int cur = kt & 1;
        const bool last = (kt == ktmax - 1);

        // K(kt) ready (V(kt) may still be in flight)
        asm volatile("cp.async.wait_group 1;\n");
        __syncthreads();

        // prefetch K(kt+1) into alt buffer
        if (!last) {
#pragma unroll
            for (int t = 0; t < 4; t++) {
                int cid = tid + t * 512;
                int row = cid >> 5, ch = cid & 31;
                cp_async16(&Ks[(cur ^ 1) * 64 * KST + row * KST + ch * 4],
                           g_k + (size_t)((kt + 1) * 64 + row) * (NKV * HD) +
                               (size_t)kvh * HD + ch * 4);
            }
            asm volatile("cp.async.commit_group;\n");
        }

        // ---- GEMM1: S[4 rows][4 cols] over d=128, packed pairs ----
        const float* Kb = Ks + cur * 64 * KST;
        unsigned long long S2[4][4] = {};
#pragma unroll 4
        for (int d = 0; d < 128; d += 4) {
            ulonglong2 qp[4], kp[4];
#pragma unroll
            for (int i = 0; i < 4; i++)
                qp[i] = *(const ulonglong2*)&Qs[(tm * 4 + i) * QST + d];
#pragma unroll
            for (int j = 0; j < 4; j++)
                kp[j] = *(const ulonglong2*)&Kb[(tn + 16 * j) * KST + d];
#pragma unroll
            for (int i = 0; i < 4; i++)
#pragma unroll
                for (int j = 0; j < 4; j++) {
                    ffma2(S2[i][j], qp[i].x, kp[j].x);
                    ffma2(S2[i][j], qp[i].y, kp[j].y);
                }
        }

        // ---- tile softmax (online), write P transposed ----
        const bool diag = (kt >= 2 * qb);
        float scl[4];
#pragma unroll
        for (int i = 0; i < 4; i++) {
            float s[4];
#pragma unroll
            for (int j = 0; j < 4; j++) {
                float2 u = unpack2(S2[i][j]);
                s[j] = (u.x + u.y) * SCALE;
            }
            if (diag) {
                int rowg = m0 + tm * 4 + i;
#pragma unroll
                for (int j = 0; j < 4; j++)
                    if (kt * 64 + tn + 16 * j > rowg) s[j] = -1e30f;
            }
            float t = fmaxf(fmaxf(s[0], s[1]), fmaxf(s[2], s[3]));
#pragma unroll
            for (int off = 1; off < 16; off <<= 1)
                t = fmaxf(t, __shfl_xor_sync(0xffffffffu, t, off));
            float nm = fmaxf(mi[i], t);
            scl[i] = __expf(mi[i] - nm);
            mi[i] = nm;
            float p0 = __expf(s[0] - nm);
            float p1 = __expf(s[1] - nm);
            float p2 = __expf(s[2] - nm);
            float p3 = __expf(s[3] - nm);
            float rs = (p0 + p1) + (p2 + p3);
#pragma unroll
            for (int off = 1; off < 16; off <<= 1)
                rs += __shfl_xor_sync(0xffffffffu, rs, off);
            li[i] = li[i] * scl[i] + rs;
            Pt[(tn     ) * PTST + tm * 4 + i] = p0;
            Pt[(tn + 16) * PTST + tm * 4 + i] = p1;
            Pt[(tn + 32) * PTST + tm * 4 + i] = p2;
            Pt[(tn + 48) * PTST + tm * 4 + i] = p3;
        }

        // V(kt) ready + Pt visible after one barrier
        if (last) asm volatile("cp.async.wait_group 0;\n");
        else      asm volatile("cp.async.wait_group 1;\n");
        __syncthreads();

        // rescale PV accumulators (packed)
#pragma unroll
        for (int i = 0; i < 4; i++) {
            unsigned long long s2 = pack2(scl[i]);
            mul2(accv[i][0], s2);
            mul2(accv[i][1], s2);
            mul2(accv[i][2], s2);
            mul2(accv[i][3], s2);
        }

        // ---- GEMM2: acc[4 rows][8 d] += P^T x V over 64 keys, packed ----
#pragma unroll 4
        for (int k = 0; k < 64; k++) {
            ulonglong2 v0 = *(const ulonglong2*)&Vs[k * KST + 4 * tn];
            ulonglong2 v1 = *(const ulonglong2*)&Vs[k * KST + 64 + 4 * tn];
            float4 pa = *(const float4*)&Pt[k * PTST + tm * 4];
            float pv[4] = {pa.x, pa.y, pa.z, pa.w};
#pragma unroll
            for (int i = 0; i < 4; i++) {
                unsigned long long pp = pack2(pv[i]);
                ffma2(accv[i][0], pp, v0.x);
                ffma2(accv[i][1], pp, v0.y);
                ffma2(accv[i][2], pp, v1.x);
                ffma2(accv[i][3], pp, v1.y);
            }
        }
        __syncthreads();   // Vs and Pt free for next tile

        // pipeline V(kt+1) into the single V buffer
        if (!last) {
#pragma unroll
            for (int t = 0; t < 4; t++) {
                int cid = tid + t * 512;
                int row = cid >> 5, ch = cid & 31;
                cp_async16(&Vs[row * KST + ch * 4],
                           g_v + (size_t)((kt + 1) * 64 + row) * (NKV * HD) +
                               (size_t)kvh * HD + ch * 4);
            }
            asm volatile("cp.async.commit_group;\n");
        }
    }

    // ---- epilogue: normalize and store ----
#pragma unroll
    for (int i = 0; i < 4; i++) {
        float inv = __fdiv_rn(1.0f, li[i]);
        float2 a0 = unpack2(accv[i][0]);
        float2 a1 = unpack2(accv[i][1]);
        float2 a2 = unpack2(accv[i][2]);
        float2 a3 = unpack2(accv[i][3]);
        float* dst = &g_attn[(size_t)(m0 + tm * 4 + i) * (NH * HD) + h * HD];
        float4 o;
        o.x = a0.x * inv; o.y = a0.y * inv; o.z = a1.x * inv; o.w = a1.y * inv;
        *(float4*)&dst[4 * tn] = o;
        o.x = a2.x * inv; o.y = a2.y * inv; o.z = a3.x * inv; o.w = a3.y * inv;
        *(float4*)&dst[64 + 4 * tn] = o;
    }
}

// ---------------------------------------------------------------------------
// Host launch
// ---------------------------------------------------------------------------
extern "C" void kernel_launch(void* const* d_in, const int* in_sizes, int n_in,
                              void* d_out, int out_size) {
    (void)in_sizes; (void)n_in; (void)out_size;
    const float* hx   = (const float*)d_in[0];
    const float* cosb = (const float*)d_in[1];
    const float* sinb = (const float*)d_in[2];
    const float* Wq   = (const float*)d_in[3];
    const float* Wk   = (const float*)d_in[4];
    const float* Wv   = (const float*)d_in[5];
    const float* Wo   = (const float*)d_in[6];
    float* out = (float*)d_out;

    void *p_xq, *p_sx, *p_wq, *p_swq, *p_wk, *p_swk, *p_wv, *p_swv, *p_wo, *p_swo;
    void *p_q, *p_k, *p_v, *p_attn, *p_aq, *p_sa;
    cudaGetSymbolAddress(&p_xq, g_xq);   cudaGetSymbolAddress(&p_sx, g_sx);
    cudaGetSymbolAddress(&p_wq, g_wq);   cudaGetSymbolAddress(&p_swq, g_swq);
    cudaGetSymbolAddress(&p_wk, g_wk);   cudaGetSymbolAddress(&p_swk, g_swk);
    cudaGetSymbolAddress(&p_wv, g_wv);   cudaGetSymbolAddress(&p_swv, g_swv);
    cudaGetSymbolAddress(&p_wo, g_wo);   cudaGetSymbolAddress(&p_swo, g_swo);
    cudaGetSymbolAddress(&p_q, g_q);     cudaGetSymbolAddress(&p_k, g_k);
    cudaGetSymbolAddress(&p_v, g_v);     cudaGetSymbolAddress(&p_attn, g_attn);
    cudaGetSymbolAddress(&p_aq, g_aq);   cudaGetSymbolAddress(&p_sa, g_sa);

    cudaFuncSetAttribute(gemm_i8mma_kernel,
                         cudaFuncAttributeMaxDynamicSharedMemorySize, GEMM_SMEM);
    cudaFuncSetAttribute(attn4_kernel,
                         cudaFuncAttributeMaxDynamicSharedMemorySize, ATTN3_SMEM);

    // 1. fake-quant activations and weights
    quant_rows_kernel<<<SEQ, 256>>>(hx, (int*)p_xq, (float*)p_sx);
    quant_rows_kernel<<<NH * HD, 256>>>(Wq, (int*)p_wq, (float*)p_swq);
    quant_rows_kernel<<<NKV * HD, 256>>>(Wk, (int*)p_wk, (float*)p_swk);
    quant_rows_kernel<<<NKV * HD, 256>>>(Wv, (int*)p_wv, (float*)p_swv);
    quant_rows_kernel<<<HDIM, 256>>>(Wo, (int*)p_wo, (float*)p_swo);

    // 2. Q projection; K+V fused via blockIdx.z
    gemm_i8mma_kernel<<<dim3((NH * HD) / 128, SEQ / 128, 1), 256, GEMM_SMEM>>>(
        (const int*)p_xq, (const float*)p_sx,
        (const int*)p_wq, (const float*)p_swq, (float*)p_q,
        (const int*)p_wq, (const float*)p_swq, (float*)p_q, NH * HD);
    gemm_i8mma_kernel<<<dim3((NKV * HD) / 128, SEQ / 128, 2), 256, GEMM_SMEM>>>(
        (const int*)p_xq, (const float*)p_sx,
        (const int*)p_wk, (const float*)p_swk, (float*)p_k,
        (const int*)p_wv, (const float*)p_swv, (float*)p_v, NKV * HD);

    // 3. RoPE (Q and K fused in one launch)
    rope_all_kernel<<<(SEQ * (NH + NKV) * 64 + 255) / 256, 256>>>(
        (float*)p_q, (float*)p_k, cosb, sinb);

    // 4. causal GQA flash attention v4 (512 threads, heavy-first)
    attn4_kernel<<<(SEQ / 128) * NH, 512, ATTN3_SMEM>>>();

    // 5. fake-quant attention output, then O projection into d_out
    quant_rows_kernel<<<SEQ, 256>>>((const float*)p_attn, (int*)p_aq, (float*)p_sa);
    gemm_i8mma_kernel<<<dim3(HDIM / 128, SEQ / 128, 1), 256, GEMM_SMEM>>>(
        (const int*)p_aq, (const float*)p_sa,
        (const int*)p_wo, (const float*)p_swo, out,
        (const int*)p_wo, (const float*)p_swo, out, HDIM);
}

// round 8
// speedup vs baseline: 4.7106x; 1.0116x over previous
#include <cuda_runtime.h>
#include <math_constants.h>
#include <cstdint>

#define SEQ   2048
#define HDIM  4096
#define NH    32
#define NKV   8
#define HD    128
#define KINT  1024          // HDIM / 4 bytes packed per int
#define SCALE 0.08838834764831845f   // 1/sqrt(128)

// ---------------------------------------------------------------------------
// Scratch (static device globals; no runtime allocation)
// ---------------------------------------------------------------------------
__device__ int   g_xq[SEQ * KINT];          // quantized hidden (int8 packed)
__device__ float g_sx[SEQ];
__device__ int   g_wq[(NH * HD) * KINT];
__device__ float g_swq[NH * HD];
__device__ int   g_wk[(NKV * HD) * KINT];
__device__ float g_swk[NKV * HD];
__device__ int   g_wv[(NKV * HD) * KINT];
__device__ float g_swv[NKV * HD];
__device__ int   g_wo[HDIM * KINT];
__device__ float g_swo[HDIM];
__device__ float g_q[SEQ * NH * HD];
__device__ float g_k[SEQ * NKV * HD];
__device__ float g_v[SEQ * NKV * HD];
__device__ float g_attn[SEQ * NH * HD];
__device__ int   g_aq[SEQ * KINT];
__device__ float g_sa[SEQ];

// ---------------------------------------------------------------------------
// Per-row fake-quant: amax/127 scale, round-half-even, pack 4x int8 into int.
// ---------------------------------------------------------------------------
__global__ void quant_rows_kernel(const float* __restrict__ in,
                                  int* __restrict__ outp,
                                  float* __restrict__ scales) {
    const int row = blockIdx.x;
    const int t = threadIdx.x;
    const float4* inr = (const float4*)(in + (size_t)row * HDIM);

    float4 v[4];
    float amax = 0.f;
#pragma unroll
    for (int l = 0; l < 4; l++) {
        v[l] = inr[t + 256 * l];
        amax = fmaxf(amax, fmaxf(fmaxf(fabsf(v[l].x), fabsf(v[l].y)),
                                 fmaxf(fabsf(v[l].z), fabsf(v[l].w))));
    }
    __shared__ float red[256];
    red[t] = amax;
    __syncthreads();
#pragma unroll
    for (int st = 128; st > 0; st >>= 1) {
        if (t < st) red[t] = fmaxf(red[t], red[t + st]);
        __syncthreads();
    }
    float s = __fdiv_rn(red[0], 127.0f);
    s = fmaxf(s, 1e-8f);
    if (t == 0) scales[row] = s;

#pragma unroll
    for (int l = 0; l < 4; l++) {
        float4 x = v[l];
        int a = (int)fminf(fmaxf(rintf(__fdiv_rn(x.x, s)), -128.f), 127.f);
        int b = (int)fminf(fmaxf(rintf(__fdiv_rn(x.y, s)), -128.f), 127.f);
        int c = (int)fminf(fmaxf(rintf(__fdiv_rn(x.z, s)), -128.f), 127.f);
        int d = (int)fminf(fmaxf(rintf(__fdiv_rn(x.w, s)), -128.f), 127.f);
        int p = (a & 0xFF) | ((b & 0xFF) << 8) | ((c & 0xFF) << 16) | (d << 24);
        outp[(size_t)row * KINT + t + 256 * l] = p;
    }
}

// ---------------------------------------------------------------------------
// Int8 tensor-core GEMM (exact): 128x128 tiles, BK=128 bytes (32 ints),
// cp.async double buffer in DYNAMIC shared memory (72KB), 32 iterations.
// ---------------------------------------------------------------------------
#define SMS2 36
#define GEMM_BUFSTRIDE (128 * SMS2)
#define GEMM_SMEM (2 * 2 * GEMM_BUFSTRIDE * 4)   // 73728 bytes

__device__ __forceinline__ void cp_async16(void* smem, const void* g) {
    uint32_t s = (uint32_t)__cvta_generic_to_shared(smem);
    asm volatile("cp.async.cg.shared.global [%0], [%1], 16;\n" :: "r"(s), "l"(g));
}

__device__ __forceinline__ void mma_i8(int& c0, int& c1, int& c2, int& c3,
                                       int a0, int a1, int a2, int a3,
                                       int b0, int b1) {
    asm volatile(
        "mma.sync.aligned.m16n8k32.row.col.s32.s8.s8.s32 "
        "{%0,%1,%2,%3}, {%4,%5,%6,%7}, {%8,%9}, {%0,%1,%2,%3};\n"
        : "+r"(c0), "+r"(c1), "+r"(c2), "+r"(c3)
        : "r"(a0), "r"(a1), "r"(a2), "r"(a3), "r"(b0), "r"(b1));
}

__global__ __launch_bounds__(256, 2)
void gemm_i8mma_kernel(const int* __restrict__ A, const float* __restrict__ sa,
                       const int* __restrict__ B0, const float* __restrict__ sb0,
                       float* __restrict__ Y0,
                       const int* __restrict__ B1, const float* __restrict__ sb1,
                       float* __restrict__ Y1, int N) {
    const int* __restrict__ B = blockIdx.z ? B1 : B0;
    const float* __restrict__ sb = blockIdx.z ? sb1 : sb0;
    float* __restrict__ Y = blockIdx.z ? Y1 : Y0;

    extern __shared__ int dynsmem[];
    int* As = dynsmem;
    int* Bs = dynsmem + 2 * GEMM_BUFSTRIDE;

    const int tid = threadIdx.x;
    const int warp = tid >> 5;
    const int lane = tid & 31;
    const int wm = warp >> 2;
    const int wn = warp & 3;
    const int lr = lane >> 2;
    const int c  = lane & 3;
    const int m0 = blockIdx.y * 128;
    const int n0 = blockIdx.x * 128;

    const int r0 = tid >> 3;
    const int ch = tid & 7;

    const int* Ag[4];
    const int* Bg[4];
    int* Asw[4];
    int* Bsw[4];
#pragma unroll
    for (int rr = 0; rr < 4; rr++) {
        int row = r0 + 32 * rr;
        Ag[rr] = A + (size_t)(m0 + row) * KINT + ch * 4;
        Bg[rr] = B + (size_t)(n0 + row) * KINT + ch * 4;
        Asw[rr] = &As[row * SMS2 + ch * 4];
        Bsw[rr] = &Bs[row * SMS2 + ch * 4];
    }

    int acc[4][4][4] = {};

#pragma unroll
    for (int rr = 0; rr < 4; rr++) {
        cp_async16(Asw[rr], Ag[rr]);
        cp_async16(Bsw[rr], Bg[rr]);
    }
    asm volatile("cp.async.commit_group;\n");

    const int* Afrag = &As[(wm * 64 + lr) * SMS2 + c];
    const int* Bfrag = &Bs[(wn * 32 + lr) * SMS2 + c];

    for (int it = 0; it < 32; it++) {
        int cur = it & 1;
        if (it < 31) {
            int nb = (it + 1) & 1;
            int ko = (it + 1) * 32;
#pragma unroll
            for (int rr = 0; rr < 4; rr++) {
                cp_async16(Asw[rr] + nb * GEMM_BUFSTRIDE, Ag[rr] + ko);
                cp_async16(Bsw[rr] + nb * GEMM_BUFSTRIDE, Bg[rr] + ko);
            }
            asm volatile("cp.async.commit_group;\n");
            asm volatile("cp.async.wait_group 1;\n");
        } else {
            asm volatile("cp.async.wait_group 0;\n");
        }
        __syncthreads();

        const int* Af = Afrag + cur * GEMM_BUFSTRIDE;
        const int* Bf = Bfrag + cur * GEMM_BUFSTRIDE;
#pragma unroll
        for (int ks = 0; ks < 4; ks++) {
            int a[4][4], b[4][2];
#pragma unroll
            for (int i = 0; i < 4; i++) {
                a[i][0] = Af[i * 16 * SMS2 + ks * 8];
                a[i][1] = Af[i * 16 * SMS2 + 8 * SMS2 + ks * 8];
                a[i][2] = Af[i * 16 * SMS2 + ks * 8 + 4];
                a[i][3] = Af[i * 16 * SMS2 + 8 * SMS2 + ks * 8 + 4];
            }
#pragma unroll
            for (int j = 0; j < 4; j++) {
                b[j][0] = Bf[j * 8 * SMS2 + ks * 8];
                b[j][1] = Bf[j * 8 * SMS2 + ks * 8 + 4];
            }
#pragma unroll
            for (int i = 0; i < 4; i++)
#pragma unroll
                for (int j = 0; j < 4; j++)
                    mma_i8(acc[i][j][0], acc[i][j][1], acc[i][j][2], acc[i][j][3],
                           a[i][0], a[i][1], a[i][2], a[i][3], b[j][0], b[j][1]);
        }
        __syncthreads();
    }

    float sav0[4], sav8[4];
#pragma unroll
    for (int i = 0; i < 4; i++) {
        sav0[i] = sa[m0 + wm * 64 + i * 16 + lr];
        sav8[i] = sa[m0 + wm * 64 + i * 16 + lr + 8];
    }
    float2 sbv[4];
#pragma unroll
    for (int j = 0; j < 4; j++) {
        int n = n0 + wn * 32 + j * 8 + 2 * c;
        sbv[j].x = sb[n];
        sbv[j].y = sb[n + 1];
    }
#pragma unroll
    for (int i = 0; i < 4; i++) {
        int mrow0 = m0 + wm * 64 + i * 16 + lr;
#pragma unroll
        for (int j = 0; j < 4; j++) {
            int n = n0 + wn * 32 + j * 8 + 2 * c;
            float2 o;
            o.x = (float)acc[i][j][0] * sav0[i] * sbv[j].x;
            o.y = (float)acc[i][j][1] * sav0[i] * sbv[j].y;
            *(float2*)&Y[(size_t)mrow0 * N + n] = o;
            o.x = (float)acc[i][j][2] * sav8[i] * sbv[j].x;
            o.y = (float)acc[i][j][3] * sav8[i] * sbv[j].y;
            *(float2*)&Y[(size_t)(mrow0 + 8) * N + n] = o;
        }
    }
}

// ---------------------------------------------------------------------------
// Fused RoPE for Q and K in one launch: virtual heads 0..39 (32 q + 8 k)
// ---------------------------------------------------------------------------
__global__ void rope_all_kernel(float* __restrict__ q, float* __restrict__ k,
                                const float* __restrict__ cosb,
                                const float* __restrict__ sinb) {
    int idx = blockIdx.x * blockDim.x + threadIdx.x;
    const int total = SEQ * (NH + NKV) * 64;
    if (idx >= total) return;
    int d = idx & 63;
    int h = (idx >> 6) % (NH + NKV);
    int t = idx / ((NH + NKV) * 64);
    float c = cosb[t * 128 + d];
    float s = sinb[t * 128 + d];
    float* p = (h < NH)
        ? q + (size_t)t * NH * 128 + h * 128 + d
        : k + (size_t)t * NKV * 128 + (h - NH) * 128 + d;
    float x1 = p[0], x2 = p[64];
    p[0]  = x1 * c - x2 * s;
    p[64] = x2 * c + x1 * s;
}

// ---------------------------------------------------------------------------
// f32x2 packed-FMA helpers (Blackwell FFMA2: 2 IEEE fp32 FMAs per instr)
// ---------------------------------------------------------------------------
__device__ __forceinline__ void ffma2(unsigned long long& d,
                                      unsigned long long a,
                                      unsigned long long b) {
    asm("fma.rn.f32x2 %0, %1, %2, %0;" : "+l"(d) : "l"(a), "l"(b));
}
__device__ __forceinline__ unsigned long long pack2(float x) {
    unsigned long long r;
    asm("mov.b64 %0, {%1, %1};" : "=l"(r) : "f"(x));
    return r;
}
__device__ __forceinline__ void mul2(unsigned long long& d, unsigned long long s) {
    asm("mul.rn.f32x2 %0, %0, %1;" : "+l"(d) : "l"(s));
}
__device__ __forceinline__ float2 unpack2(unsigned long long a) {
    float2 f;
    asm("mov.b64 {%0, %1}, %2;" : "=f"(f.x), "=f"(f.y) : "l"(a));
    return f;
}

// ---------------------------------------------------------------------------
// Causal GQA flash attention v5: ping-pong (2 blocks/SM).
// Block: 64 q-rows x head; KV tiles of 64 keys. 256 threads, ~97KB smem ->
// 2 co-resident blocks per SM overlap each other's softmax/barrier/load
// phases with FFMA2 work (v4 lesson: intra-block warps can't overlap phases
// because barriers force lockstep; blocks can).
// Pt (transposed P) ALIASES the K buffer: K is dead after GEMM1, Pt is born
// after it. Single-buffer K/V loads; partner block hides the latency.
// Thread (tm=tid>>4, tn=tid&15): q rows tm*4..+3, S cols tn+16j,
// PV d-cols 4tn..+3 and 64+4tn..+3. Per-element math identical to v4.
// ---------------------------------------------------------------------------
#define QST5 128
#define KST5 132
#define VST5 128
#define PTST5 68
#define ATTN5_SMEM ((64 * QST5 + 64 * KST5 + 64 * VST5) * 4)   // 99328 B

__global__ __launch_bounds__(256, 2) void attn5_kernel() {
    extern __shared__ float sh[];
    float* Qs = sh;                         // 64 x QST5
    float* Ks = Qs + 64 * QST5;             // 64 x KST5 (aliased by Pt)
    float* Vs = Ks + 64 * KST5;             // 64 x VST5
    float* Pt = Ks;                         // 64 x PTST5, alias (17KB < 33KB)

    const int bid = blockIdx.x;
    const int qb  = 31 - (bid >> 5);        // heavy-first
    const int h   = bid & 31;
    const int kvh = h >> 2;
    const int tid = threadIdx.x;
    const int tm  = tid >> 4;               // 0..15
    const int tn  = tid & 15;               // 0..15
    const int m0  = qb * 64;

    // ---- stage Q (64x128) + K/V tile 0 ----
#pragma unroll
    for (int t = 0; t < 8; t++) {
        int cid = tid + t * 256;            // 0..2047
        int row = cid >> 5, ch = cid & 31;
        cp_async16(&Qs[row * QST5 + ch * 4],
                   g_q + (size_t)(m0 + row) * (NH * HD) + h * HD + ch * 4);
        size_t src = (size_t)row * (NKV * HD) + (size_t)kvh * HD + ch * 4;
        cp_async16(&Ks[row * KST5 + ch * 4], g_k + src);
        cp_async16(&Vs[row * VST5 + ch * 4], g_v + src);
    }
    asm volatile("cp.async.commit_group;\n");

    float mi[4], li[4];
#pragma unroll
    for (int i = 0; i < 4; i++) { mi[i] = -1e30f; li[i] = 0.f; }
    unsigned long long accv[4][4] = {};     // [row][0,1]=d 4tn; [2,3]=64+4tn

    for (int kt = 0; kt <= qb; kt++) {
        asm volatile("cp.async.wait_group 0;\n");
        __syncthreads();

        // ---- GEMM1: S[4 rows][4 cols] over d=128, packed pairs ----
        unsigned long long S2[4][4] = {};
#pragma unroll 4
        for (int d = 0; d < 128; d += 4) {
            ulonglong2 qp[4], kp[4];
#pragma unroll
            for (int i = 0; i < 4; i++)
                qp[i] = *(const ulonglong2*)&Qs[(tm * 4 + i) * QST5 + d];
#pragma unroll
            for (int j = 0; j < 4; j++)
                kp[j] = *(const ulonglong2*)&Ks[(tn + 16 * j) * KST5 + d];
#pragma unroll
            for (int i = 0; i < 4; i++)
#pragma unroll
                for (int j = 0; j < 4; j++) {
                    ffma2(S2[i][j], qp[i].x, kp[j].x);
                    ffma2(S2[i][j], qp[i].y, kp[j].y);
                }
        }
        __syncthreads();   // all warps done reading Ks before Pt overwrites it

        // ---- tile softmax (online), write P transposed into K's space ----
        const bool diag = (kt == qb);
        float scl[4];
#pragma unroll
        for (int i = 0; i < 4; i++) {
            float s[4];
#pragma unroll
            for (int j = 0; j < 4; j++) {
                float2 u = unpack2(S2[i][j]);
                s[j] = (u.x + u.y) * SCALE;
            }
            if (diag) {
                int rowg = m0 + tm * 4 + i;
#pragma unroll
                for (int j = 0; j < 4; j++)
                    if (kt * 64 + tn + 16 * j > rowg) s[j] = -1e30f;
            }
            float t = fmaxf(fmaxf(s[0], s[1]), fmaxf(s[2], s[3]));
#pragma unroll
            for (int off = 1; off < 16; off <<= 1)
                t = fmaxf(t, __shfl_xor_sync(0xffffffffu, t, off));
            float nm = fmaxf(mi[i], t);
            scl[i] = __expf(mi[i] - nm);
            mi[i] = nm;
            float p0 = __expf(s[0] - nm);
            float p1 = __expf(s[1] - nm);
            float p2 = __expf(s[2] - nm);
            float p3 = __expf(s[3] - nm);
            float rs = (p0 + p1) + (p2 + p3);
#pragma unroll
            for (int off = 1; off < 16; off <<= 1)
                rs += __shfl_xor_sync(0xffffffffu, rs, off);
            li[i] = li[i] * scl[i] + rs;
            Pt[(tn     ) * PTST5 + tm * 4 + i] = p0;
            Pt[(tn + 16) * PTST5 + tm * 4 + i] = p1;
            Pt[(tn + 32) * PTST5 + tm * 4 + i] = p2;
            Pt[(tn + 48) * PTST5 + tm * 4 + i] = p3;
        }
        __syncthreads();   // Pt visible

        // rescale PV accumulators (packed)
#pragma unroll
        for (int i = 0; i < 4; i++) {
            unsigned long long s2 = pack2(scl[i]);
            mul2(accv[i][0], s2);
            mul2(accv[i][1], s2);
            mul2(accv[i][2], s2);
            mul2(accv[i][3], s2);
        }

        // ---- GEMM2: acc[4 rows][8 d] += P^T x V over 64 keys, packed ----
#pragma unroll 4
        for (int k = 0; k < 64; k++) {
            ulonglong2 v0 = *(const ulonglong2*)&Vs[k * VST5 + 4 * tn];
            ulonglong2 v1 = *(const ulonglong2*)&Vs[k * VST5 + 64 + 4 * tn];
            float4 pa = *(const float4*)&Pt[k * PTST5 + tm * 4];
            float pv[4] = {pa.x, pa.y, pa.z, pa.w};
#pragma unroll
            for (int i = 0; i < 4; i++) {
                unsigned long long pp = pack2(pv[i]);
                ffma2(accv[i][0], pp, v0.x);
                ffma2(accv[i][1], pp, v0.y);
                ffma2(accv[i][2], pp, v1.x);
                ffma2(accv[i][3], pp, v1.y);
            }
        }
        __syncthreads();   // Pt (=Ks) and Vs free for next tile's loads

        // issue K/V(kt+1); partner block covers the exposed latency
        if (kt < qb) {
#pragma unroll
            for (int t = 0; t < 8; t++) {
                int cid = tid + t * 256;
                int row = cid >> 5, ch = cid & 31;
                size_t src = (size_t)((kt + 1) * 64 + row) * (NKV * HD) +
                             (size_t)kvh * HD + ch * 4;
                cp_async16(&Ks[row * KST5 + ch * 4], g_k + src);
                cp_async16(&Vs[row * VST5 + ch * 4], g_v + src);
            }
            asm volatile("cp.async.commit_group;\n");
        }
    }

    // ---- epilogue: normalize and store ----
#pragma unroll
    for (int i = 0; i < 4; i++) {
        float inv = __fdiv_rn(1.0f, li[i]);
        float2 a0 = unpack2(accv[i][0]);
        float2 a1 = unpack2(accv[i][1]);
        float2 a2 = unpack2(accv[i][2]);
        float2 a3 = unpack2(accv[i][3]);
        float* dst = &g_attn[(size_t)(m0 + tm * 4 + i) * (NH * HD) + h * HD];
        float4 o;
        o.x = a0.x * inv; o.y = a0.y * inv; o.z = a1.x * inv; o.w = a1.y * inv;
        *(float4*)&dst[4 * tn] = o;
        o.x = a2.x * inv; o.y = a2.y * inv; o.z = a3.x * inv; o.w = a3.y * inv;
        *(float4*)&dst[64 + 4 * tn] = o;
    }
}

// ---------------------------------------------------------------------------
// Host launch
// ---------------------------------------------------------------------------
extern "C" void kernel_launch(void* const* d_in, const int* in_sizes, int n_in,
                              void* d_out, int out_size) {
    (void)in_sizes; (void)n_in; (void)out_size;
    const float* hx   = (const float*)d_in[0];
    const float* cosb = (const float*)d_in[1];
    const float* sinb = (const float*)d_in[2];
    const float* Wq   = (const float*)d_in[3];
    const float* Wk   = (const float*)d_in[4];
    const float* Wv   = (const float*)d_in[5];
    const float* Wo   = (const float*)d_in[6];
    float* out = (float*)d_out;

    void *p_xq, *p_sx, *p_wq, *p_swq, *p_wk, *p_swk, *p_wv, *p_swv, *p_wo, *p_swo;
    void *p_q, *p_k, *p_v, *p_attn, *p_aq, *p_sa;
    cudaGetSymbolAddress(&p_xq, g_xq);   cudaGetSymbolAddress(&p_sx, g_sx);
    cudaGetSymbolAddress(&p_wq, g_wq);   cudaGetSymbolAddress(&p_swq, g_swq);
    cudaGetSymbolAddress(&p_wk, g_wk);   cudaGetSymbolAddress(&p_swk, g_swk);
    cudaGetSymbolAddress(&p_wv, g_wv);   cudaGetSymbolAddress(&p_swv, g_swv);
    cudaGetSymbolAddress(&p_wo, g_wo);   cudaGetSymbolAddress(&p_swo, g_swo);
    cudaGetSymbolAddress(&p_q, g_q);     cudaGetSymbolAddress(&p_k, g_k);
    cudaGetSymbolAddress(&p_v, g_v);     cudaGetSymbolAddress(&p_attn, g_attn);
    cudaGetSymbolAddress(&p_aq, g_aq);   cudaGetSymbolAddress(&p_sa, g_sa);

    cudaFuncSetAttribute(gemm_i8mma_kernel,
                         cudaFuncAttributeMaxDynamicSharedMemorySize, GEMM_SMEM);
    cudaFuncSetAttribute(attn5_kernel,
                         cudaFuncAttributeMaxDynamicSharedMemorySize, ATTN5_SMEM);

    // 1. fake-quant activations and weights
    quant_rows_kernel<<<SEQ, 256>>>(hx, (int*)p_xq, (float*)p_sx);
    quant_rows_kernel<<<NH * HD, 256>>>(Wq, (int*)p_wq, (float*)p_swq);
    quant_rows_kernel<<<NKV * HD, 256>>>(Wk, (int*)p_wk, (float*)p_swk);
    quant_rows_kernel<<<NKV * HD, 256>>>(Wv, (int*)p_wv, (float*)p_swv);
    quant_rows_kernel<<<HDIM, 256>>>(Wo, (int*)p_wo, (float*)p_swo);

    // 2. Q projection; K+V fused via blockIdx.z
    gemm_i8mma_kernel<<<dim3((NH * HD) / 128, SEQ / 128, 1), 256, GEMM_SMEM>>>(
        (const int*)p_xq, (const float*)p_sx,
        (const int*)p_wq, (const float*)p_swq, (float*)p_q,
        (const int*)p_wq, (const float*)p_swq, (float*)p_q, NH * HD);
    gemm_i8mma_kernel<<<dim3((NKV * HD) / 128, SEQ / 128, 2), 256, GEMM_SMEM>>>(
        (const int*)p_xq, (const float*)p_sx,
        (const int*)p_wk, (const float*)p_swk, (float*)p_k,
        (const int*)p_wv, (const float*)p_swv, (float*)p_v, NKV * HD);

    // 3. RoPE (Q and K fused in one launch)
    rope_all_kernel<<<(SEQ * (NH + NKV) * 64 + 255) / 256, 256>>>(
        (float*)p_q, (float*)p_k, cosb, sinb);

    // 4. causal GQA flash attention v5 (ping-pong, 2 blocks/SM, heavy-first)
    attn5_kernel<<<(SEQ / 64) * NH, 256, ATTN5_SMEM>>>();

    // 5. fake-quant attention output, then O projection into d_out
    quant_rows_kernel<<<SEQ, 256>>>((const float*)p_attn, (int*)p_aq, (float*)p_sa);
    gemm_i8mma_kernel<<<dim3(HDIM / 128, SEQ / 128, 1), 256, GEMM_SMEM>>>(
        (const int*)p_aq, (const float*)p_sa,
        (const int*)p_wo, (const float*)p_swo, out,
        (const int*)p_wo, (const float*)p_swo, out, HDIM);
}